// round 1
// baseline (speedup 1.0000x reference)
#include <cuda_runtime.h>
#include <math.h>

#define NODES_MAX 50000
#define EDGES_MAX 800000
#define GRAPHS_MAX 1024

// ---------------- scratch (device globals; no allocation allowed) -------------
__device__ int   g_eidx[2 * EDGES_MAX];        // converted src|dst (int32)
__device__ int   g_batch[NODES_MAX];
__device__ int   g_deg[NODES_MAX];
__device__ int   g_rowptr[NODES_MAX + 1];
__device__ int   g_cur[NODES_MAX];
__device__ int   g_col[EDGES_MAX];
__device__ int   g_flag[1];
__device__ float g_dinv[NODES_MAX];
__device__ float g_hs[(size_t)NODES_MAX * 256];
__device__ float g_rbuf[(size_t)NODES_MAX * 256];
__device__ float g_x1[(size_t)NODES_MAX * 128];
__device__ float g_x2[(size_t)NODES_MAX * 256];
__device__ float g_x3[(size_t)NODES_MAX * 256];
__device__ float g_pool[GRAPHS_MAX * 256];
__device__ float g_fp[GRAPHS_MAX * 256];
__device__ float g_fg[GRAPHS_MAX * 256];
__device__ int   g_cnt[GRAPHS_MAX];

// ---------------- dtype detect + index convert --------------------------------
// int64 little-endian values < 50000 => every odd 32-bit word is 0.
__global__ void detect_kernel(const unsigned int* __restrict__ w, int* __restrict__ flag) {
    int t = threadIdx.x;  // 32 threads
    unsigned int v = w[2 * t + 1] | w[2 * (t + 32) + 1] | w[2 * (t + 64) + 1] | w[2 * (t + 96) + 1];
    unsigned int nz = __ballot_sync(0xFFFFFFFFu, v != 0u);
    if (t == 0) *flag = (nz == 0u) ? 1 : 0;
}

__global__ void cvt_idx_kernel(const void* __restrict__ raw, int n,
                               const int* __restrict__ flag, int* __restrict__ out) {
    int i = blockIdx.x * blockDim.x + threadIdx.x;
    if (i >= n) return;
    if (*flag) out[i] = (int)((const long long*)raw)[i];
    else       out[i] = ((const int*)raw)[i];
}

// ---------------- degree / dinv / CSR ------------------------------------------
__global__ void deg_kernel(const int* __restrict__ dst, int E, int* __restrict__ deg) {
    int i = blockIdx.x * blockDim.x + threadIdx.x;
    if (i < E) atomicAdd(&deg[dst[i]], 1);
}

__global__ void dinv_kernel(const int* __restrict__ deg, float* __restrict__ dinv, int n) {
    int i = blockIdx.x * blockDim.x + threadIdx.x;
    if (i < n) dinv[i] = rsqrtf((float)deg[i] + 1.0f);
}

__global__ void scan_kernel(const int* __restrict__ deg, int* __restrict__ rowptr, int n) {
    __shared__ int sums[1024];
    int t = threadIdx.x;
    int chunk = (n + 1023) / 1024;
    int s = t * chunk;
    int e = min(s + chunk, n);
    int acc = 0;
    for (int i = s; i < e; i++) acc += deg[i];
    sums[t] = acc;
    __syncthreads();
    for (int d = 1; d < 1024; d <<= 1) {
        int v = (t >= d) ? sums[t - d] : 0;
        __syncthreads();
        sums[t] += v;
        __syncthreads();
    }
    int off = (t == 0) ? 0 : sums[t - 1];
    for (int i = s; i < e; i++) { rowptr[i] = off; off += deg[i]; }
    if (t == 1023) rowptr[n] = sums[1023];
}

__global__ void fill_csr_kernel(const int* __restrict__ src, const int* __restrict__ dst, int E,
                                const int* __restrict__ rowptr, int* __restrict__ cur,
                                int* __restrict__ col) {
    int i = blockIdx.x * blockDim.x + threadIdx.x;
    if (i >= E) return;
    int d = dst[i];
    int pos = rowptr[d] + atomicAdd(&cur[d], 1);
    col[pos] = src[i];
}

// ---------------- generic fp32 GEMM: C = A[MxK] * B[KxN] ----------------------
// Epilogue: optional per-row dinv scaling (cols < scale_cols), bias, relu, or
// atomic-accumulate (for split-K).
__global__ __launch_bounds__(256, 2) void gemm_kernel(
    const float* __restrict__ A, const float* __restrict__ B, float* __restrict__ C,
    int M, int N, int K, int kChunk,
    const float* __restrict__ dinv, int scale_cols,
    const float* __restrict__ bias, int relu, int atomicOut)
{
    const int BM = 128, BN = 128, BK = 16, TM = 8, TN = 8;
    __shared__ float As[BK][BM];
    __shared__ float Bs[BK][BN];
    int tid = threadIdx.x;
    int rowBase = blockIdx.y * BM;
    int colBase = blockIdx.x * BN;
    int kStart = blockIdx.z * kChunk;
    int kEnd = min(K, kStart + kChunk);

    int tr = (tid / 16) * TM;
    int tc = (tid % 16) * TN;

    int aRow = tid / 4;          // 0..63 (+64 for second)
    int aCol = (tid % 4) * 4;    // 0,4,8,12
    int bRow = tid / 32;         // 0..7 (+8)
    int bCol = (tid % 32) * 4;   // 0..124

    float acc[TM][TN];
    #pragma unroll
    for (int i = 0; i < TM; i++)
        #pragma unroll
        for (int j = 0; j < TN; j++) acc[i][j] = 0.f;

    bool kAligned = ((K & 3) == 0);

    for (int k0 = kStart; k0 < kEnd; k0 += BK) {
        #pragma unroll
        for (int i = 0; i < 2; i++) {
            int r = rowBase + aRow + i * 64;
            int cb = k0 + aCol;
            float4 v = make_float4(0.f, 0.f, 0.f, 0.f);
            if (r < M) {
                if (kAligned && (cb + 3 < kEnd)) {
                    v = *(const float4*)(A + (size_t)r * K + cb);
                } else {
                    float t0 = (cb + 0 < kEnd) ? A[(size_t)r * K + cb + 0] : 0.f;
                    float t1 = (cb + 1 < kEnd) ? A[(size_t)r * K + cb + 1] : 0.f;
                    float t2 = (cb + 2 < kEnd) ? A[(size_t)r * K + cb + 2] : 0.f;
                    float t3 = (cb + 3 < kEnd) ? A[(size_t)r * K + cb + 3] : 0.f;
                    v = make_float4(t0, t1, t2, t3);
                }
            }
            As[aCol + 0][aRow + i * 64] = v.x;
            As[aCol + 1][aRow + i * 64] = v.y;
            As[aCol + 2][aRow + i * 64] = v.z;
            As[aCol + 3][aRow + i * 64] = v.w;
        }
        #pragma unroll
        for (int i = 0; i < 2; i++) {
            int r = k0 + bRow + i * 8;
            float4 v = make_float4(0.f, 0.f, 0.f, 0.f);
            if (r < kEnd) v = *(const float4*)(B + (size_t)r * N + colBase + bCol);
            *(float4*)(&Bs[bRow + i * 8][bCol]) = v;
        }
        __syncthreads();

        #pragma unroll
        for (int kk = 0; kk < BK; kk++) {
            float av[TM], bv[TN];
            #pragma unroll
            for (int i = 0; i < TM; i++) av[i] = As[kk][tr + i];
            #pragma unroll
            for (int j = 0; j < TN; j++) bv[j] = Bs[kk][tc + j];
            #pragma unroll
            for (int i = 0; i < TM; i++)
                #pragma unroll
                for (int j = 0; j < TN; j++) acc[i][j] += av[i] * bv[j];
        }
        __syncthreads();
    }

    #pragma unroll
    for (int i = 0; i < TM; i++) {
        int r = rowBase + tr + i;
        if (r >= M) continue;
        float dv = (scale_cols > 0) ? dinv[r] : 1.0f;
        #pragma unroll
        for (int j = 0; j < TN; j++) {
            int c = colBase + tc + j;
            float v = acc[i][j];
            if (atomicOut) { atomicAdd(&C[(size_t)r * N + c], v); continue; }
            if (c < scale_cols) v *= dv;
            if (bias) v += bias[c];
            if (relu) v = fmaxf(v, 0.f);
            C[(size_t)r * N + c] = v;
        }
    }
}

// ---------------- per-node CSR aggregation + epilogue --------------------------
// out[v] = relu( dinv[v]*(hs[v] + sum_{u in nbrs(v)} hs[u]) + bias (+ res[v] + rbias) )
template <int C, bool HASRES>
__global__ void aggregate_kernel(const float* __restrict__ hs, const float* __restrict__ res,
                                 const int* __restrict__ rowptr, const int* __restrict__ col,
                                 const float* __restrict__ dinv,
                                 const float* __restrict__ bias, const float* __restrict__ rbias,
                                 float* __restrict__ out, int n)
{
    int warp = (blockIdx.x * blockDim.x + threadIdx.x) >> 5;
    if (warp >= n) return;
    int lane = threadIdx.x & 31;
    const int F = C / 32;     // floats per lane (4 or 8)
    const int V = F / 4;      // float4s per lane

    float acc[F];
    const float4* self = (const float4*)(hs + (size_t)warp * C + lane * F);
    #pragma unroll
    for (int j = 0; j < V; j++) {
        float4 v = self[j];
        acc[4 * j + 0] = v.x; acc[4 * j + 1] = v.y; acc[4 * j + 2] = v.z; acc[4 * j + 3] = v.w;
    }

    int s = rowptr[warp], e = rowptr[warp + 1];
    int k = s;
    for (; k + 1 < e; k += 2) {
        int u0 = col[k], u1 = col[k + 1];
        const float4* p0 = (const float4*)(hs + (size_t)u0 * C + lane * F);
        const float4* p1 = (const float4*)(hs + (size_t)u1 * C + lane * F);
        #pragma unroll
        for (int j = 0; j < V; j++) {
            float4 a = p0[j], b = p1[j];
            acc[4 * j + 0] += a.x + b.x;
            acc[4 * j + 1] += a.y + b.y;
            acc[4 * j + 2] += a.z + b.z;
            acc[4 * j + 3] += a.w + b.w;
        }
    }
    if (k < e) {
        int u = col[k];
        const float4* p = (const float4*)(hs + (size_t)u * C + lane * F);
        #pragma unroll
        for (int j = 0; j < V; j++) {
            float4 a = p[j];
            acc[4 * j + 0] += a.x; acc[4 * j + 1] += a.y;
            acc[4 * j + 2] += a.z; acc[4 * j + 3] += a.w;
        }
    }

    float dv = dinv[warp];
    float* orow = out + (size_t)warp * C + lane * F;
    const float* rrow = HASRES ? (res + (size_t)warp * C + lane * F) : nullptr;
    #pragma unroll
    for (int j = 0; j < F; j++) {
        float v = dv * acc[j] + bias[lane * F + j];
        if (HASRES) v += rrow[j] + rbias[lane * F + j];
        orow[j] = fmaxf(v, 0.f);
    }
}

// ---------------- softmax(attn) * x3, pooled segment-sum -----------------------
__global__ void softmax_pool_kernel(const float* __restrict__ logits, const float* __restrict__ x3,
                                    const int* __restrict__ batch,
                                    float* __restrict__ pooled, int* __restrict__ cnt, int n)
{
    int warp = (blockIdx.x * blockDim.x + threadIdx.x) >> 5;
    if (warp >= n) return;
    int lane = threadIdx.x & 31;
    const float4* lr = (const float4*)(logits + (size_t)warp * 256 + lane * 8);
    float4 a0 = lr[0], a1 = lr[1];
    float a[8] = {a0.x, a0.y, a0.z, a0.w, a1.x, a1.y, a1.z, a1.w};
    float m = a[0];
    #pragma unroll
    for (int j = 1; j < 8; j++) m = fmaxf(m, a[j]);
    #pragma unroll
    for (int off = 16; off > 0; off >>= 1) m = fmaxf(m, __shfl_xor_sync(0xFFFFFFFFu, m, off));
    float s = 0.f;
    #pragma unroll
    for (int j = 0; j < 8; j++) { a[j] = __expf(a[j] - m); s += a[j]; }
    #pragma unroll
    for (int off = 16; off > 0; off >>= 1) s += __shfl_xor_sync(0xFFFFFFFFu, s, off);
    float inv = 1.f / s;
    const float4* xr = (const float4*)(x3 + (size_t)warp * 256 + lane * 8);
    float4 x0 = xr[0], x1 = xr[1];
    float xv[8] = {x0.x, x0.y, x0.z, x0.w, x1.x, x1.y, x1.z, x1.w};
    int g = batch[warp];
    float* pr = pooled + (size_t)g * 256 + lane * 8;
    #pragma unroll
    for (int j = 0; j < 8; j++) atomicAdd(pr + j, a[j] * inv * xv[j]);
    if (lane == 0) atomicAdd(&cnt[g], 1);
}

// ---------------- final: (pooled/cnt + relu(fp+bfp) + relu(fg+bfg)) @ Wfc + bfc -
__global__ void final_kernel(const float* __restrict__ pooled, const int* __restrict__ cnt,
                             const float* __restrict__ fpa, const float* __restrict__ fga,
                             const float* __restrict__ bfp, const float* __restrict__ bfg,
                             const float* __restrict__ Wfc, const float* __restrict__ bfc,
                             float* __restrict__ out, int B)
{
    int warp = (blockIdx.x * blockDim.x + threadIdx.x) >> 5;
    if (warp >= B) return;
    int lane = threadIdx.x & 31;
    float invc = 1.f / fmaxf((float)cnt[warp], 1.f);
    float s = 0.f;
    #pragma unroll
    for (int j = 0; j < 8; j++) {
        int idx = lane * 8 + j;
        size_t o = (size_t)warp * 256 + idx;
        float v = pooled[o] * invc
                + fmaxf(fpa[o] + bfp[idx], 0.f)
                + fmaxf(fga[o] + bfg[idx], 0.f);
        s += v * Wfc[idx];
    }
    #pragma unroll
    for (int off = 16; off > 0; off >>= 1) s += __shfl_xor_sync(0xFFFFFFFFu, s, off);
    if (lane == 0) out[warp] = s + bfc[0];
}

// ---------------- host launcher -------------------------------------------------
static inline void launch_gemm(const float* A, const float* B, float* C,
                               int M, int N, int K, int kChunk, int zs,
                               const float* dinv, int scale_cols,
                               const float* bias, int relu, int atomicOut)
{
    dim3 grid(N / 128, (M + 127) / 128, zs);
    gemm_kernel<<<grid, 256>>>(A, B, C, M, N, K, kChunk, dinv, scale_cols, bias, relu, atomicOut);
}

extern "C" void kernel_launch(void* const* d_in, const int* in_sizes, int n_in,
                              void* d_out, int out_size)
{
    const float* x    = (const float*)d_in[0];
    const void*  eraw = d_in[1];
    const void*  braw = d_in[2];
    const float* fpf  = (const float*)d_in[3];
    const float* fgf  = (const float*)d_in[4];
    const float* W1   = (const float*)d_in[5];  const float* b1  = (const float*)d_in[6];
    const float* W2   = (const float*)d_in[7];  const float* b2  = (const float*)d_in[8];
    const float* W3   = (const float*)d_in[9];  const float* b3  = (const float*)d_in[10];
    const float* Wr1  = (const float*)d_in[11]; const float* br1 = (const float*)d_in[12];
    const float* Wr2  = (const float*)d_in[13]; const float* br2 = (const float*)d_in[14];
    const float* Wfp  = (const float*)d_in[15]; const float* bfp = (const float*)d_in[16];
    const float* Wfg  = (const float*)d_in[17]; const float* bfg = (const float*)d_in[18];
    const float* attn_W = (const float*)d_in[19];
    const float* Wfc  = (const float*)d_in[20]; const float* bfc = (const float*)d_in[21];
    float* out = (float*)d_out;

    int N = in_sizes[0] / 64;
    int E = in_sizes[1] / 2;
    int B = in_sizes[3] / 2048;

    float *hs, *rbuf, *x1, *x2, *x3, *dinv, *pooled, *fp, *fg;
    int *eidx, *batch, *deg, *rowptr, *cur, *col, *cnt, *flag;
    cudaGetSymbolAddress((void**)&eidx,   g_eidx);
    cudaGetSymbolAddress((void**)&batch,  g_batch);
    cudaGetSymbolAddress((void**)&deg,    g_deg);
    cudaGetSymbolAddress((void**)&rowptr, g_rowptr);
    cudaGetSymbolAddress((void**)&cur,    g_cur);
    cudaGetSymbolAddress((void**)&col,    g_col);
    cudaGetSymbolAddress((void**)&flag,   g_flag);
    cudaGetSymbolAddress((void**)&dinv,   g_dinv);
    cudaGetSymbolAddress((void**)&hs,     g_hs);
    cudaGetSymbolAddress((void**)&rbuf,   g_rbuf);
    cudaGetSymbolAddress((void**)&x1,     g_x1);
    cudaGetSymbolAddress((void**)&x2,     g_x2);
    cudaGetSymbolAddress((void**)&x3,     g_x3);
    cudaGetSymbolAddress((void**)&pooled, g_pool);
    cudaGetSymbolAddress((void**)&fp,     g_fp);
    cudaGetSymbolAddress((void**)&fg,     g_fg);
    cudaGetSymbolAddress((void**)&cnt,    g_cnt);

    cudaMemsetAsync(deg,    0, N * sizeof(int));
    cudaMemsetAsync(cur,    0, N * sizeof(int));
    cudaMemsetAsync(pooled, 0, (size_t)B * 256 * sizeof(float));
    cudaMemsetAsync(cnt,    0, B * sizeof(int));
    cudaMemsetAsync(fp,     0, (size_t)B * 256 * sizeof(float));
    cudaMemsetAsync(fg,     0, (size_t)B * 256 * sizeof(float));

    // dtype detect + index conversion
    detect_kernel<<<1, 32>>>((const unsigned int*)eraw, flag);
    cvt_idx_kernel<<<(2 * E + 255) / 256, 256>>>(eraw, 2 * E, flag, eidx);
    cvt_idx_kernel<<<(N + 255) / 256, 256>>>(braw, N, flag, batch);
    const int* srcA = eidx;
    const int* dstA = eidx + E;

    // degree / dinv / CSR
    deg_kernel<<<(E + 255) / 256, 256>>>(dstA, E, deg);
    dinv_kernel<<<(N + 255) / 256, 256>>>(deg, dinv, N);
    scan_kernel<<<1, 1024>>>(deg, rowptr, N);
    fill_csr_kernel<<<(E + 255) / 256, 256>>>(srcA, dstA, E, rowptr, cur, col);

    int aggBlocks = (N * 32 + 255) / 256;

    // Layer 1: hs = (x @ W1) * dinv ; x1 = relu(agg + b1)
    launch_gemm(x, W1, hs, N, 128, 64, 64, 1, dinv, 128, nullptr, 0, 0);
    aggregate_kernel<128, false><<<aggBlocks, 256>>>(hs, nullptr, rowptr, col, dinv, b1, nullptr, x1, N);

    // Layer 2: hs = (x1 @ W2)*dinv ; r = x1 @ Wr1 ; x2 = relu(agg + b2 + r + br1)
    launch_gemm(x1, W2,  hs,   N, 256, 128, 128, 1, dinv, 256, nullptr, 0, 0);
    launch_gemm(x1, Wr1, rbuf, N, 256, 128, 128, 1, nullptr, 0, nullptr, 0, 0);
    aggregate_kernel<256, true><<<aggBlocks, 256>>>(hs, rbuf, rowptr, col, dinv, b2, br1, x2, N);

    // Layer 3
    launch_gemm(x2, W3,  hs,   N, 256, 256, 256, 1, dinv, 256, nullptr, 0, 0);
    launch_gemm(x2, Wr2, rbuf, N, 256, 256, 256, 1, nullptr, 0, nullptr, 0, 0);
    aggregate_kernel<256, true><<<aggBlocks, 256>>>(hs, rbuf, rowptr, col, dinv, b3, br2, x3, N);

    // Attention logits: hs = x3 @ attn_W
    launch_gemm(x3, attn_W, hs, N, 256, 256, 256, 1, nullptr, 0, nullptr, 0, 0);

    // fp: split-K (K=2048 -> 8 chunks) atomic accumulate; bias+relu in final kernel
    launch_gemm(fpf, Wfp, fp, B, 256, 2048, 256, 8, nullptr, 0, nullptr, 0, 1);
    // fg: K=167
    launch_gemm(fgf, Wfg, fg, B, 256, 167, 167, 1, nullptr, 0, nullptr, 0, 1);

    // softmax * x3 -> pooled segment sum
    softmax_pool_kernel<<<aggBlocks, 256>>>(hs, x3, batch, pooled, cnt, N);

    // final projection
    final_kernel<<<(B * 32 + 255) / 256, 256>>>(pooled, cnt, fp, fg, bfp, bfg, Wfc, bfc, out, B);
}

// round 2
// speedup vs baseline: 1.5599x; 1.5599x over previous
#include <cuda_runtime.h>
#include <mma.h>
#include <math.h>

using namespace nvcuda;

#define NODES_MAX 50000
#define EDGES_MAX 800000
#define GRAPHS_MAX 1024

// ---------------- scratch (device globals; no allocation allowed) -------------
__device__ int   g_eidx[2 * EDGES_MAX];
__device__ int   g_batch[NODES_MAX];
__device__ int   g_deg[NODES_MAX];
__device__ int   g_rowptr[NODES_MAX + 1];
__device__ int   g_cur[NODES_MAX];
__device__ int   g_col[EDGES_MAX];
__device__ int   g_flag[1];
__device__ float g_dinv[NODES_MAX];
__device__ float g_hs[(size_t)NODES_MAX * 256];
__device__ float g_rbuf[(size_t)NODES_MAX * 256];
__device__ float g_x1[(size_t)NODES_MAX * 128];
__device__ float g_x2[(size_t)NODES_MAX * 256];
__device__ float g_x3[(size_t)NODES_MAX * 256];
__device__ float g_pool[GRAPHS_MAX * 256];
__device__ float g_fp[GRAPHS_MAX * 256];
__device__ float g_fg[GRAPHS_MAX * 256];

// ---------------- dtype detect + index convert --------------------------------
__global__ void detect_kernel(const unsigned int* __restrict__ w, int* __restrict__ flag) {
    int t = threadIdx.x;
    unsigned int v = w[2 * t + 1] | w[2 * (t + 32) + 1] | w[2 * (t + 64) + 1] | w[2 * (t + 96) + 1];
    unsigned int nz = __ballot_sync(0xFFFFFFFFu, v != 0u);
    if (t == 0) *flag = (nz == 0u) ? 1 : 0;
}

__global__ void cvt_idx_kernel(const void* __restrict__ raw, int n,
                               const int* __restrict__ flag, int* __restrict__ out) {
    int i = blockIdx.x * blockDim.x + threadIdx.x;
    if (i >= n) return;
    if (*flag) out[i] = (int)((const long long*)raw)[i];
    else       out[i] = ((const int*)raw)[i];
}

// ---------------- degree / dinv / CSR ------------------------------------------
__global__ void deg_kernel(const int* __restrict__ dst, int E, int* __restrict__ deg) {
    int i = blockIdx.x * blockDim.x + threadIdx.x;
    if (i < E) atomicAdd(&deg[dst[i]], 1);
}

__global__ void dinv_kernel(const int* __restrict__ deg, float* __restrict__ dinv, int n) {
    int i = blockIdx.x * blockDim.x + threadIdx.x;
    if (i < n) dinv[i] = rsqrtf((float)deg[i] + 1.0f);
}

__global__ void scan_kernel(const int* __restrict__ deg, int* __restrict__ rowptr, int n) {
    __shared__ int sums[1024];
    int t = threadIdx.x;
    int chunk = (n + 1023) / 1024;
    int s = t * chunk;
    int e = min(s + chunk, n);
    int acc = 0;
    for (int i = s; i < e; i++) acc += deg[i];
    sums[t] = acc;
    __syncthreads();
    for (int d = 1; d < 1024; d <<= 1) {
        int v = (t >= d) ? sums[t - d] : 0;
        __syncthreads();
        sums[t] += v;
        __syncthreads();
    }
    int off = (t == 0) ? 0 : sums[t - 1];
    for (int i = s; i < e; i++) { rowptr[i] = off; off += deg[i]; }
    if (t == 1023) rowptr[n] = sums[1023];
}

__global__ void fill_csr_kernel(const int* __restrict__ src, const int* __restrict__ dst, int E,
                                const int* __restrict__ rowptr, int* __restrict__ cur,
                                int* __restrict__ col) {
    int i = blockIdx.x * blockDim.x + threadIdx.x;
    if (i >= E) return;
    int d = dst[i];
    int pos = rowptr[d] + atomicAdd(&cur[d], 1);
    col[pos] = src[i];
}

// ---------------- tf32 tensor-core GEMM: C = A[MxK] * B[KxN] -------------------
// BM=128, BN=128, BK=16, 8 warps (2x4), warp tile 64x32 via wmma m16n16k8 tf32.
__global__ __launch_bounds__(256, 2) void gemm_tc_kernel(
    const float* __restrict__ A, const float* __restrict__ B, float* __restrict__ C,
    int M, int N, int K, int kChunk,
    const float* __restrict__ dinv, int scale_cols,
    const float* __restrict__ bias, int relu, int atomicOut)
{
    const int BM = 128, BN = 128, BK = 16;
    const int LDA = BK + 4;   // 20
    const int LDB = BN + 4;   // 132
    __shared__ __align__(16) float As[BM * LDA];       // 10240 B
    __shared__ __align__(16) float Bs[BK * LDB];       // 8448 B
    __shared__ __align__(16) float Es[8 * 16 * 20];    // per-warp epilogue scratch

    int tid  = threadIdx.x;
    int lane = tid & 31;
    int warp = tid >> 5;
    int wr = warp >> 2;                 // 0..1
    int wc = warp & 3;                  // 0..3
    int warpM = wr * 64;
    int warpN = wc * 32;

    int rowBase = blockIdx.y * BM;
    int colBase = blockIdx.x * BN;
    int kStart  = blockIdx.z * kChunk;
    int kEnd    = min(K, kStart + kChunk);

    wmma::fragment<wmma::accumulator, 16, 16, 8, float> acc[4][2];
    #pragma unroll
    for (int m = 0; m < 4; m++)
        #pragma unroll
        for (int n = 0; n < 2; n++) wmma::fill_fragment(acc[m][n], 0.0f);

    bool kAligned = ((K & 3) == 0);

    int aRow = tid >> 1;               // 0..127
    int aCol = (tid & 1) * 8;          // 0 or 8
    int bRow = tid >> 4;               // 0..15
    int bCol = (tid & 15) * 8;         // 0..120

    for (int k0 = kStart; k0 < kEnd; k0 += BK) {
        // stage A tile (128 x 16), tf32-converted, zero-padded out of range
        {
            int r = rowBase + aRow;
            #pragma unroll
            for (int j = 0; j < 2; j++) {
                int cb = k0 + aCol + j * 4;
                float4 v = make_float4(0.f, 0.f, 0.f, 0.f);
                if (r < M) {
                    if (kAligned && (cb + 3 < kEnd)) {
                        v = *(const float4*)(A + (size_t)r * K + cb);
                    } else {
                        if (cb + 0 < kEnd) v.x = A[(size_t)r * K + cb + 0];
                        if (cb + 1 < kEnd) v.y = A[(size_t)r * K + cb + 1];
                        if (cb + 2 < kEnd) v.z = A[(size_t)r * K + cb + 2];
                        if (cb + 3 < kEnd) v.w = A[(size_t)r * K + cb + 3];
                    }
                }
                float* dstp = As + aRow * LDA + aCol + j * 4;
                dstp[0] = wmma::__float_to_tf32(v.x);
                dstp[1] = wmma::__float_to_tf32(v.y);
                dstp[2] = wmma::__float_to_tf32(v.z);
                dstp[3] = wmma::__float_to_tf32(v.w);
            }
        }
        // stage B tile (16 x 128)
        {
            int kr = k0 + bRow;
            #pragma unroll
            for (int j = 0; j < 2; j++) {
                float4 v = make_float4(0.f, 0.f, 0.f, 0.f);
                if (kr < kEnd) v = *(const float4*)(B + (size_t)kr * N + colBase + bCol + j * 4);
                float* dstp = Bs + bRow * LDB + bCol + j * 4;
                dstp[0] = wmma::__float_to_tf32(v.x);
                dstp[1] = wmma::__float_to_tf32(v.y);
                dstp[2] = wmma::__float_to_tf32(v.z);
                dstp[3] = wmma::__float_to_tf32(v.w);
            }
        }
        __syncthreads();

        #pragma unroll
        for (int kk = 0; kk < BK; kk += 8) {
            wmma::fragment<wmma::matrix_a, 16, 16, 8, wmma::precision::tf32, wmma::row_major> af[4];
            wmma::fragment<wmma::matrix_b, 16, 16, 8, wmma::precision::tf32, wmma::row_major> bf[2];
            #pragma unroll
            for (int m = 0; m < 4; m++)
                wmma::load_matrix_sync(af[m], As + (warpM + 16 * m) * LDA + kk, LDA);
            #pragma unroll
            for (int n = 0; n < 2; n++)
                wmma::load_matrix_sync(bf[n], Bs + kk * LDB + warpN + 16 * n, LDB);
            #pragma unroll
            for (int m = 0; m < 4; m++)
                #pragma unroll
                for (int n = 0; n < 2; n++)
                    wmma::mma_sync(acc[m][n], af[m], bf[n], acc[m][n]);
        }
        __syncthreads();
    }

    // epilogue: per-warp 16x16 tile staging through smem
    float* es = Es + warp * 320;   // 16*20
    #pragma unroll
    for (int m = 0; m < 4; m++) {
        #pragma unroll
        for (int n = 0; n < 2; n++) {
            wmma::store_matrix_sync(es, acc[m][n], 20, wmma::mem_row_major);
            __syncwarp();
            #pragma unroll
            for (int i = 0; i < 2; i++) {
                int r  = i * 8 + (lane >> 2);
                int c4 = (lane & 3) * 4;
                int gr = rowBase + warpM + 16 * m + r;
                int gc = colBase + warpN + 16 * n + c4;
                if (gr < M) {
                    float4 v = *(float4*)(es + r * 20 + c4);
                    if (atomicOut) {
                        float* cp = C + (size_t)gr * N + gc;
                        atomicAdd(cp + 0, v.x);
                        atomicAdd(cp + 1, v.y);
                        atomicAdd(cp + 2, v.z);
                        atomicAdd(cp + 3, v.w);
                    } else {
                        float dv = (scale_cols > 0) ? dinv[gr] : 1.0f;
                        if (gc < scale_cols) { v.x *= dv; v.y *= dv; v.z *= dv; v.w *= dv; }
                        if (bias) { v.x += bias[gc]; v.y += bias[gc+1]; v.z += bias[gc+2]; v.w += bias[gc+3]; }
                        if (relu) {
                            v.x = fmaxf(v.x, 0.f); v.y = fmaxf(v.y, 0.f);
                            v.z = fmaxf(v.z, 0.f); v.w = fmaxf(v.w, 0.f);
                        }
                        *(float4*)(C + (size_t)gr * N + gc) = v;
                    }
                }
            }
            __syncwarp();
        }
    }
}

// ---------------- per-node CSR aggregation + epilogue --------------------------
template <int C, bool HASRES>
__global__ void aggregate_kernel(const float* __restrict__ hs, const float* __restrict__ res,
                                 const int* __restrict__ rowptr, const int* __restrict__ col,
                                 const float* __restrict__ dinv,
                                 const float* __restrict__ bias, const float* __restrict__ rbias,
                                 float* __restrict__ out, int n)
{
    int warp = (blockIdx.x * blockDim.x + threadIdx.x) >> 5;
    if (warp >= n) return;
    int lane = threadIdx.x & 31;
    const int F = C / 32;
    const int V = F / 4;

    float acc[F];
    const float4* self = (const float4*)(hs + (size_t)warp * C + lane * F);
    #pragma unroll
    for (int j = 0; j < V; j++) {
        float4 v = self[j];
        acc[4 * j + 0] = v.x; acc[4 * j + 1] = v.y; acc[4 * j + 2] = v.z; acc[4 * j + 3] = v.w;
    }

    int s = rowptr[warp], e = rowptr[warp + 1];
    int k = s;
    for (; k + 1 < e; k += 2) {
        int u0 = col[k], u1 = col[k + 1];
        const float4* p0 = (const float4*)(hs + (size_t)u0 * C + lane * F);
        const float4* p1 = (const float4*)(hs + (size_t)u1 * C + lane * F);
        #pragma unroll
        for (int j = 0; j < V; j++) {
            float4 a = p0[j], b = p1[j];
            acc[4 * j + 0] += a.x + b.x;
            acc[4 * j + 1] += a.y + b.y;
            acc[4 * j + 2] += a.z + b.z;
            acc[4 * j + 3] += a.w + b.w;
        }
    }
    if (k < e) {
        int u = col[k];
        const float4* p = (const float4*)(hs + (size_t)u * C + lane * F);
        #pragma unroll
        for (int j = 0; j < V; j++) {
            float4 a = p[j];
            acc[4 * j + 0] += a.x; acc[4 * j + 1] += a.y;
            acc[4 * j + 2] += a.z; acc[4 * j + 3] += a.w;
        }
    }

    float dv = dinv[warp];
    float* orow = out + (size_t)warp * C + lane * F;
    const float* rrow = HASRES ? (res + (size_t)warp * C + lane * F) : nullptr;
    #pragma unroll
    for (int j = 0; j < F; j++) {
        float v = dv * acc[j] + bias[lane * F + j];
        if (HASRES) v += rrow[j] + rbias[lane * F + j];
        orow[j] = fmaxf(v, 0.f);
    }
}

// ---------------- softmax * x3, per-graph pooled mean (no atomics) -------------
__device__ __forceinline__ int lowerb(const int* a, int n, int key) {
    int lo = 0, hi = n;
    while (lo < hi) { int mid = (lo + hi) >> 1; if (a[mid] < key) lo = mid + 1; else hi = mid; }
    return lo;
}

__global__ void softmax_pool_kernel(const float* __restrict__ logits, const float* __restrict__ x3,
                                    const int* __restrict__ batch,
                                    float* __restrict__ pooled, int n)
{
    __shared__ float sred[8 * 256];
    int g = blockIdx.x;
    int lane = threadIdx.x & 31;
    int w = threadIdx.x >> 5;

    int start = lowerb(batch, n, g);
    int end   = lowerb(batch, n, g + 1);

    float acc[8];
    #pragma unroll
    for (int j = 0; j < 8; j++) acc[j] = 0.f;

    for (int node = start + w; node < end; node += 8) {
        const float4* lr = (const float4*)(logits + (size_t)node * 256 + lane * 8);
        float4 a0 = lr[0], a1 = lr[1];
        float a[8] = {a0.x, a0.y, a0.z, a0.w, a1.x, a1.y, a1.z, a1.w};
        float m = a[0];
        #pragma unroll
        for (int j = 1; j < 8; j++) m = fmaxf(m, a[j]);
        #pragma unroll
        for (int off = 16; off > 0; off >>= 1) m = fmaxf(m, __shfl_xor_sync(0xFFFFFFFFu, m, off));
        float s = 0.f;
        #pragma unroll
        for (int j = 0; j < 8; j++) { a[j] = __expf(a[j] - m); s += a[j]; }
        #pragma unroll
        for (int off = 16; off > 0; off >>= 1) s += __shfl_xor_sync(0xFFFFFFFFu, s, off);
        float inv = 1.f / s;
        const float4* xr = (const float4*)(x3 + (size_t)node * 256 + lane * 8);
        float4 x0 = xr[0], x1 = xr[1];
        float xv[8] = {x0.x, x0.y, x0.z, x0.w, x1.x, x1.y, x1.z, x1.w};
        #pragma unroll
        for (int j = 0; j < 8; j++) acc[j] += a[j] * inv * xv[j];
    }

    #pragma unroll
    for (int j = 0; j < 8; j++) sred[w * 256 + lane * 8 + j] = acc[j];
    __syncthreads();

    int t = threadIdx.x;
    float v = 0.f;
    #pragma unroll
    for (int ww = 0; ww < 8; ww++) v += sred[ww * 256 + t];
    float invc = 1.f / fmaxf((float)(end - start), 1.f);
    pooled[(size_t)g * 256 + t] = v * invc;
}

// ---------------- final: (pooled + relu(fp+bfp) + relu(fg+bfg)) @ Wfc + bfc ----
__global__ void final_kernel(const float* __restrict__ pooled,
                             const float* __restrict__ fpa, const float* __restrict__ fga,
                             const float* __restrict__ bfp, const float* __restrict__ bfg,
                             const float* __restrict__ Wfc, const float* __restrict__ bfc,
                             float* __restrict__ out, int B)
{
    int warp = (blockIdx.x * blockDim.x + threadIdx.x) >> 5;
    if (warp >= B) return;
    int lane = threadIdx.x & 31;
    float s = 0.f;
    #pragma unroll
    for (int j = 0; j < 8; j++) {
        int idx = lane * 8 + j;
        size_t o = (size_t)warp * 256 + idx;
        float v = pooled[o]
                + fmaxf(fpa[o] + bfp[idx], 0.f)
                + fmaxf(fga[o] + bfg[idx], 0.f);
        s += v * Wfc[idx];
    }
    #pragma unroll
    for (int off = 16; off > 0; off >>= 1) s += __shfl_xor_sync(0xFFFFFFFFu, s, off);
    if (lane == 0) out[warp] = s + bfc[0];
}

// ---------------- host launcher -------------------------------------------------
static inline void launch_gemm(const float* A, const float* B, float* C,
                               int M, int N, int K, int kChunk, int zs,
                               const float* dinv, int scale_cols,
                               const float* bias, int relu, int atomicOut)
{
    dim3 grid(N / 128, (M + 127) / 128, zs);
    gemm_tc_kernel<<<grid, 256>>>(A, B, C, M, N, K, kChunk, dinv, scale_cols, bias, relu, atomicOut);
}

extern "C" void kernel_launch(void* const* d_in, const int* in_sizes, int n_in,
                              void* d_out, int out_size)
{
    const float* x    = (const float*)d_in[0];
    const void*  eraw = d_in[1];
    const void*  braw = d_in[2];
    const float* fpf  = (const float*)d_in[3];
    const float* fgf  = (const float*)d_in[4];
    const float* W1   = (const float*)d_in[5];  const float* b1  = (const float*)d_in[6];
    const float* W2   = (const float*)d_in[7];  const float* b2  = (const float*)d_in[8];
    const float* W3   = (const float*)d_in[9];  const float* b3  = (const float*)d_in[10];
    const float* Wr1  = (const float*)d_in[11]; const float* br1 = (const float*)d_in[12];
    const float* Wr2  = (const float*)d_in[13]; const float* br2 = (const float*)d_in[14];
    const float* Wfp  = (const float*)d_in[15]; const float* bfp = (const float*)d_in[16];
    const float* Wfg  = (const float*)d_in[17]; const float* bfg = (const float*)d_in[18];
    const float* attn_W = (const float*)d_in[19];
    const float* Wfc  = (const float*)d_in[20]; const float* bfc = (const float*)d_in[21];
    float* out = (float*)d_out;

    int N = in_sizes[0] / 64;
    int E = in_sizes[1] / 2;
    int B = in_sizes[3] / 2048;

    float *hs, *rbuf, *x1, *x2, *x3, *dinv, *pooled, *fp, *fg;
    int *eidx, *batch, *deg, *rowptr, *cur, *col, *flag;
    cudaGetSymbolAddress((void**)&eidx,   g_eidx);
    cudaGetSymbolAddress((void**)&batch,  g_batch);
    cudaGetSymbolAddress((void**)&deg,    g_deg);
    cudaGetSymbolAddress((void**)&rowptr, g_rowptr);
    cudaGetSymbolAddress((void**)&cur,    g_cur);
    cudaGetSymbolAddress((void**)&col,    g_col);
    cudaGetSymbolAddress((void**)&flag,   g_flag);
    cudaGetSymbolAddress((void**)&dinv,   g_dinv);
    cudaGetSymbolAddress((void**)&hs,     g_hs);
    cudaGetSymbolAddress((void**)&rbuf,   g_rbuf);
    cudaGetSymbolAddress((void**)&x1,     g_x1);
    cudaGetSymbolAddress((void**)&x2,     g_x2);
    cudaGetSymbolAddress((void**)&x3,     g_x3);
    cudaGetSymbolAddress((void**)&pooled, g_pool);
    cudaGetSymbolAddress((void**)&fp,     g_fp);
    cudaGetSymbolAddress((void**)&fg,     g_fg);

    cudaMemsetAsync(deg, 0, N * sizeof(int));
    cudaMemsetAsync(cur, 0, N * sizeof(int));
    cudaMemsetAsync(fp,  0, (size_t)B * 256 * sizeof(float));
    cudaMemsetAsync(fg,  0, (size_t)B * 256 * sizeof(float));

    // dtype detect + index conversion
    detect_kernel<<<1, 32>>>((const unsigned int*)eraw, flag);
    cvt_idx_kernel<<<(2 * E + 255) / 256, 256>>>(eraw, 2 * E, flag, eidx);
    cvt_idx_kernel<<<(N + 255) / 256, 256>>>(braw, N, flag, batch);
    const int* srcA = eidx;
    const int* dstA = eidx + E;

    // degree / dinv / CSR
    deg_kernel<<<(E + 255) / 256, 256>>>(dstA, E, deg);
    dinv_kernel<<<(N + 255) / 256, 256>>>(deg, dinv, N);
    scan_kernel<<<1, 1024>>>(deg, rowptr, N);
    fill_csr_kernel<<<(E + 255) / 256, 256>>>(srcA, dstA, E, rowptr, cur, col);

    int aggBlocks = (N * 32 + 255) / 256;

    // Layer 1
    launch_gemm(x, W1, hs, N, 128, 64, 64, 1, dinv, 128, nullptr, 0, 0);
    aggregate_kernel<128, false><<<aggBlocks, 256>>>(hs, nullptr, rowptr, col, dinv, b1, nullptr, x1, N);

    // Layer 2
    launch_gemm(x1, W2,  hs,   N, 256, 128, 128, 1, dinv, 256, nullptr, 0, 0);
    launch_gemm(x1, Wr1, rbuf, N, 256, 128, 128, 1, nullptr, 0, nullptr, 0, 0);
    aggregate_kernel<256, true><<<aggBlocks, 256>>>(hs, rbuf, rowptr, col, dinv, b2, br1, x2, N);

    // Layer 3
    launch_gemm(x2, W3,  hs,   N, 256, 256, 256, 1, dinv, 256, nullptr, 0, 0);
    launch_gemm(x2, Wr2, rbuf, N, 256, 256, 256, 1, nullptr, 0, nullptr, 0, 0);
    aggregate_kernel<256, true><<<aggBlocks, 256>>>(hs, rbuf, rowptr, col, dinv, b3, br2, x3, N);

    // Attention logits
    launch_gemm(x3, attn_W, hs, N, 256, 256, 256, 1, nullptr, 0, nullptr, 0, 0);

    // fp: split-K atomic accumulate; fg: single chunk
    launch_gemm(fpf, Wfp, fp, B, 256, 2048, 256, 8, nullptr, 0, nullptr, 0, 1);
    launch_gemm(fgf, Wfg, fg, B, 256, 167, 167, 1, nullptr, 0, nullptr, 0, 1);

    // softmax * x3 -> per-graph pooled mean (block per graph, no atomics)
    softmax_pool_kernel<<<B, 256>>>(hs, x3, batch, pooled, N);

    // final projection
    final_kernel<<<(B * 32 + 255) / 256, 256>>>(pooled, fp, fg, bfp, bfg, Wfc, bfc, out, B);
}

// round 4
// speedup vs baseline: 1.6525x; 1.0593x over previous
#include <cuda_runtime.h>
#include <cstdint>
#include <mma.h>
#include <math.h>

using namespace nvcuda;

#define NODES_MAX 50000
#define EDGES_MAX 800000
#define GRAPHS_MAX 1024

// ---------------- scratch (device globals; no allocation allowed) -------------
__device__ int   g_eidx[2 * EDGES_MAX];
__device__ int   g_batch[NODES_MAX];
__device__ int   g_deg[NODES_MAX];
__device__ int   g_rowptr[NODES_MAX + 1];
__device__ int   g_cur[NODES_MAX];
__device__ int   g_col[EDGES_MAX];
__device__ int   g_flag[1];
__device__ float g_dinv[NODES_MAX];
__device__ float g_work[(size_t)NODES_MAX * 512];   // GEMM outputs (hs | res)
__device__ float g_x1[(size_t)NODES_MAX * 128];
__device__ float g_x2[(size_t)NODES_MAX * 256];
__device__ float g_x3[(size_t)NODES_MAX * 256];
__device__ float g_xr[(size_t)NODES_MAX * 64];      // tf32-rounded input x
__device__ float g_wc1[64 * 128];
__device__ float g_wc2[128 * 512];                  // [W2 | Wr1]
__device__ float g_wc3[256 * 512];                  // [W3 | Wr2]
__device__ float g_wattn[256 * 256];
__device__ float g_pool[GRAPHS_MAX * 256];
__device__ float g_fp[GRAPHS_MAX * 256];
__device__ float g_fg[GRAPHS_MAX * 256];

__device__ __forceinline__ float tf32r(float x) {
    float r;
    asm("cvt.rna.tf32.f32 %0, %1;" : "=f"(r) : "f"(x));
    return r;
}

__device__ __forceinline__ void cp16(uint32_t dst, const void* src, bool pred) {
    int bytes = pred ? 16 : 0;
    asm volatile("cp.async.cg.shared.global [%0], [%1], 16, %2;\n"
                 :: "r"(dst), "l"(src), "r"(bytes));
}
__device__ __forceinline__ void cp_commit() { asm volatile("cp.async.commit_group;\n"); }
__device__ __forceinline__ void cp_wait1()  { asm volatile("cp.async.wait_group 1;\n"); }

// ---------------- dtype detect + index convert --------------------------------
__global__ void detect_kernel(const unsigned int* __restrict__ w, int* __restrict__ flag) {
    int t = threadIdx.x;
    unsigned int v = w[2 * t + 1] | w[2 * (t + 32) + 1] | w[2 * (t + 64) + 1] | w[2 * (t + 96) + 1];
    unsigned int nz = __ballot_sync(0xFFFFFFFFu, v != 0u);
    if (t == 0) *flag = (nz == 0u) ? 1 : 0;
}

// converts both src and dst, and counts degree on dst
__global__ void cvt_edges_kernel(const void* __restrict__ raw, int E,
                                 const int* __restrict__ flag, int* __restrict__ eidx,
                                 int* __restrict__ deg) {
    int i = blockIdx.x * blockDim.x + threadIdx.x;
    if (i >= E) return;
    int s, d;
    if (*flag) {
        s = (int)((const long long*)raw)[i];
        d = (int)((const long long*)raw)[E + i];
    } else {
        s = ((const int*)raw)[i];
        d = ((const int*)raw)[E + i];
    }
    eidx[i] = s;
    eidx[E + i] = d;
    atomicAdd(&deg[d], 1);
}

__global__ void cvt_idx_kernel(const void* __restrict__ raw, int n,
                               const int* __restrict__ flag, int* __restrict__ out) {
    int i = blockIdx.x * blockDim.x + threadIdx.x;
    if (i >= n) return;
    if (*flag) out[i] = (int)((const long long*)raw)[i];
    else       out[i] = ((const int*)raw)[i];
}

// ---------------- rounding / weight concat -------------------------------------
__global__ void round_tf32_kernel(const float* __restrict__ in, float* __restrict__ out, int n) {
    int i = blockIdx.x * blockDim.x + threadIdx.x;
    if (i < n) out[i] = tf32r(in[i]);
}

__global__ void concat2_tf32_kernel(const float* __restrict__ B1, const float* __restrict__ B2,
                                    float* __restrict__ out, int K) {
    int i = blockIdx.x * blockDim.x + threadIdx.x;
    if (i >= K * 512) return;
    int k = i >> 9, c = i & 511;
    float v = (c < 256) ? B1[k * 256 + c] : B2[k * 256 + (c - 256)];
    out[i] = tf32r(v);
}

// ---------------- degree / dinv / CSR ------------------------------------------
__global__ void dinv_kernel(const int* __restrict__ deg, float* __restrict__ dinv, int n) {
    int i = blockIdx.x * blockDim.x + threadIdx.x;
    if (i < n) dinv[i] = rsqrtf((float)deg[i] + 1.0f);
}

__global__ void scan_kernel(const int* __restrict__ deg, int* __restrict__ rowptr, int n) {
    __shared__ int sums[1024];
    int t = threadIdx.x;
    int chunk = (n + 1023) / 1024;
    int s = t * chunk;
    int e = min(s + chunk, n);
    int acc = 0;
    for (int i = s; i < e; i++) acc += deg[i];
    sums[t] = acc;
    __syncthreads();
    for (int d = 1; d < 1024; d <<= 1) {
        int v = (t >= d) ? sums[t - d] : 0;
        __syncthreads();
        sums[t] += v;
        __syncthreads();
    }
    int off = (t == 0) ? 0 : sums[t - 1];
    for (int i = s; i < e; i++) { rowptr[i] = off; off += deg[i]; }
    if (t == 1023) rowptr[n] = sums[1023];
}

__global__ void fill_csr_kernel(const int* __restrict__ src, const int* __restrict__ dst, int E,
                                const int* __restrict__ rowptr, int* __restrict__ cur,
                                int* __restrict__ col) {
    int i = blockIdx.x * blockDim.x + threadIdx.x;
    if (i >= E) return;
    int d = dst[i];
    int pos = rowptr[d] + atomicAdd(&cur[d], 1);
    col[pos] = src[i];
}

// ---------------- pipelined tf32 GEMM (inputs pre-rounded to tf32) -------------
// C[M x N] = A[M x K] * B[K x N]; K % 16 == 0, N % 128 == 0, rows of A 16B-aligned.
// Epilogue: cols < scale_cols multiplied by dinv[row]; output row stride ldc.
__global__ __launch_bounds__(256, 2) void gemm_pipe_kernel(
    const float* __restrict__ A, const float* __restrict__ B, float* __restrict__ C,
    int M, int N, int K, int ldc,
    const float* __restrict__ dinv, int scale_cols)
{
    const int BM = 128, BK = 16;
    const int LDA = 20, LDB = 132;
    __shared__ __align__(16) float As[2][BM * LDA];   // 2 * 10240 B
    __shared__ __align__(16) float Bs[2][BK * LDB];   // 2 * 8448 B

    int tid  = threadIdx.x;
    int lane = tid & 31;
    int warp = tid >> 5;
    int warpM = (warp >> 2) * 64;
    int warpN = (warp & 3) * 32;
    int rowBase = blockIdx.y * BM;
    int colBase = blockIdx.x * 128;

    wmma::fragment<wmma::accumulator, 16, 16, 8, float> acc[4][2];
    #pragma unroll
    for (int m = 0; m < 4; m++)
        #pragma unroll
        for (int n = 0; n < 2; n++) wmma::fill_fragment(acc[m][n], 0.0f);

    int ntiles = K / BK;

    uint32_t asBase[2], bsBase[2];
    asBase[0] = (uint32_t)__cvta_generic_to_shared(&As[0][0]);
    asBase[1] = (uint32_t)__cvta_generic_to_shared(&As[1][0]);
    bsBase[0] = (uint32_t)__cvta_generic_to_shared(&Bs[0][0]);
    bsBase[1] = (uint32_t)__cvta_generic_to_shared(&Bs[1][0]);

    auto issue = [&](int t, int s) {
        int k0 = t * BK;
        #pragma unroll
        for (int h = 0; h < 2; h++) {
            int c = tid + h * 256;
            int row = c >> 2, q = c & 3;
            int r = rowBase + row;
            bool ok = (r < M);
            const float* src = A + (size_t)(ok ? r : 0) * K + k0 + q * 4;
            cp16(asBase[s] + (uint32_t)(row * LDA + q * 4) * 4u, src, ok);
        }
        #pragma unroll
        for (int h = 0; h < 2; h++) {
            int c = tid + h * 256;
            int row = c >> 5, q = c & 31;
            const float* src = B + (size_t)(k0 + row) * N + colBase + q * 4;
            cp16(bsBase[s] + (uint32_t)(row * LDB + q * 4) * 4u, src, true);
        }
    };

    issue(0, 0);
    cp_commit();

    for (int t = 0; t < ntiles; t++) {
        if (t + 1 < ntiles) issue(t + 1, (t + 1) & 1);
        cp_commit();
        cp_wait1();
        __syncthreads();

        const float* as = As[t & 1];
        const float* bs = Bs[t & 1];
        #pragma unroll
        for (int kk = 0; kk < BK; kk += 8) {
            wmma::fragment<wmma::matrix_a, 16, 16, 8, wmma::precision::tf32, wmma::row_major> af[4];
            wmma::fragment<wmma::matrix_b, 16, 16, 8, wmma::precision::tf32, wmma::row_major> bf[2];
            #pragma unroll
            for (int m = 0; m < 4; m++)
                wmma::load_matrix_sync(af[m], as + (warpM + 16 * m) * LDA + kk, LDA);
            #pragma unroll
            for (int n = 0; n < 2; n++)
                wmma::load_matrix_sync(bf[n], bs + kk * LDB + warpN + 16 * n, LDB);
            #pragma unroll
            for (int m = 0; m < 4; m++)
                #pragma unroll
                for (int n = 0; n < 2; n++)
                    wmma::mma_sync(acc[m][n], af[m], bf[n], acc[m][n]);
        }
        __syncthreads();
    }

    // epilogue via smem staging (reuse As[0]; all warps synced above)
    float* es = &As[0][0] + warp * 320;
    #pragma unroll
    for (int m = 0; m < 4; m++) {
        #pragma unroll
        for (int n = 0; n < 2; n++) {
            wmma::store_matrix_sync(es, acc[m][n], 20, wmma::mem_row_major);
            __syncwarp();
            #pragma unroll
            for (int i = 0; i < 2; i++) {
                int r  = i * 8 + (lane >> 2);
                int c4 = (lane & 3) * 4;
                int gr = rowBase + warpM + 16 * m + r;
                int gc = colBase + warpN + 16 * n + c4;
                if (gr < M) {
                    float4 v = *(float4*)(es + r * 20 + c4);
                    if (gc < scale_cols) {
                        float dv = dinv[gr];
                        v.x *= dv; v.y *= dv; v.z *= dv; v.w *= dv;
                    }
                    *(float4*)(C + (size_t)gr * ldc + gc) = v;
                }
            }
            __syncwarp();
        }
    }
}

// ---------------- legacy tf32 GEMM (handles K tails / bias / atomics) ----------
__global__ __launch_bounds__(256, 2) void gemm_tc_kernel(
    const float* __restrict__ A, const float* __restrict__ B, float* __restrict__ C,
    int M, int N, int K, int kChunk, int atomicOut)
{
    const int BM = 128, BN = 128, BK = 16;
    const int LDA = 20, LDB = 132;
    __shared__ __align__(16) float As[BM * LDA];
    __shared__ __align__(16) float Bs[BK * LDB];

    int tid  = threadIdx.x;
    int lane = tid & 31;
    int warp = tid >> 5;
    int warpM = (warp >> 2) * 64;
    int warpN = (warp & 3) * 32;

    int rowBase = blockIdx.y * BM;
    int colBase = blockIdx.x * BN;
    int kStart  = blockIdx.z * kChunk;
    int kEnd    = min(K, kStart + kChunk);

    wmma::fragment<wmma::accumulator, 16, 16, 8, float> acc[4][2];
    #pragma unroll
    for (int m = 0; m < 4; m++)
        #pragma unroll
        for (int n = 0; n < 2; n++) wmma::fill_fragment(acc[m][n], 0.0f);

    bool kAligned = ((K & 3) == 0);
    int aRow = tid >> 1, aCol = (tid & 1) * 8;
    int bRow = tid >> 4, bCol = (tid & 15) * 8;

    for (int k0 = kStart; k0 < kEnd; k0 += BK) {
        {
            int r = rowBase + aRow;
            #pragma unroll
            for (int j = 0; j < 2; j++) {
                int cb = k0 + aCol + j * 4;
                float4 v = make_float4(0.f, 0.f, 0.f, 0.f);
                if (r < M) {
                    if (kAligned && (cb + 3 < kEnd)) {
                        v = *(const float4*)(A + (size_t)r * K + cb);
                    } else {
                        if (cb + 0 < kEnd) v.x = A[(size_t)r * K + cb + 0];
                        if (cb + 1 < kEnd) v.y = A[(size_t)r * K + cb + 1];
                        if (cb + 2 < kEnd) v.z = A[(size_t)r * K + cb + 2];
                        if (cb + 3 < kEnd) v.w = A[(size_t)r * K + cb + 3];
                    }
                }
                float* dstp = As + aRow * LDA + aCol + j * 4;
                dstp[0] = tf32r(v.x); dstp[1] = tf32r(v.y);
                dstp[2] = tf32r(v.z); dstp[3] = tf32r(v.w);
            }
        }
        {
            int kr = k0 + bRow;
            #pragma unroll
            for (int j = 0; j < 2; j++) {
                float4 v = make_float4(0.f, 0.f, 0.f, 0.f);
                if (kr < kEnd) v = *(const float4*)(B + (size_t)kr * N + colBase + bCol + j * 4);
                float* dstp = Bs + bRow * LDB + bCol + j * 4;
                dstp[0] = tf32r(v.x); dstp[1] = tf32r(v.y);
                dstp[2] = tf32r(v.z); dstp[3] = tf32r(v.w);
            }
        }
        __syncthreads();

        #pragma unroll
        for (int kk = 0; kk < BK; kk += 8) {
            wmma::fragment<wmma::matrix_a, 16, 16, 8, wmma::precision::tf32, wmma::row_major> af[4];
            wmma::fragment<wmma::matrix_b, 16, 16, 8, wmma::precision::tf32, wmma::row_major> bf[2];
            #pragma unroll
            for (int m = 0; m < 4; m++)
                wmma::load_matrix_sync(af[m], As + (warpM + 16 * m) * LDA + kk, LDA);
            #pragma unroll
            for (int n = 0; n < 2; n++)
                wmma::load_matrix_sync(bf[n], Bs + kk * LDB + warpN + 16 * n, LDB);
            #pragma unroll
            for (int m = 0; m < 4; m++)
                #pragma unroll
                for (int n = 0; n < 2; n++)
                    wmma::mma_sync(acc[m][n], af[m], bf[n], acc[m][n]);
        }
        __syncthreads();
    }

    float* es = As + warp * 320;
    #pragma unroll
    for (int m = 0; m < 4; m++) {
        #pragma unroll
        for (int n = 0; n < 2; n++) {
            wmma::store_matrix_sync(es, acc[m][n], 20, wmma::mem_row_major);
            __syncwarp();
            #pragma unroll
            for (int i = 0; i < 2; i++) {
                int r  = i * 8 + (lane >> 2);
                int c4 = (lane & 3) * 4;
                int gr = rowBase + warpM + 16 * m + r;
                int gc = colBase + warpN + 16 * n + c4;
                if (gr < M) {
                    float4 v = *(float4*)(es + r * 20 + c4);
                    float* cp = C + (size_t)gr * N + gc;
                    if (atomicOut) {
                        atomicAdd(cp + 0, v.x); atomicAdd(cp + 1, v.y);
                        atomicAdd(cp + 2, v.z); atomicAdd(cp + 3, v.w);
                    } else {
                        *(float4*)cp = v;
                    }
                }
            }
            __syncwarp();
        }
    }
}

// ---------------- per-node CSR aggregation + epilogue (tf32-rounded out) ------
template <int C, bool HASRES>
__global__ void aggregate_kernel(const float* __restrict__ hs, const float* __restrict__ res,
                                 int ldh,
                                 const int* __restrict__ rowptr, const int* __restrict__ col,
                                 const float* __restrict__ dinv,
                                 const float* __restrict__ bias, const float* __restrict__ rbias,
                                 float* __restrict__ out, int n)
{
    int warp = (blockIdx.x * blockDim.x + threadIdx.x) >> 5;
    if (warp >= n) return;
    int lane = threadIdx.x & 31;
    const int F = C / 32;
    const int V = F / 4;

    float acc[F];
    const float4* self = (const float4*)(hs + (size_t)warp * ldh + lane * F);
    #pragma unroll
    for (int j = 0; j < V; j++) {
        float4 v = self[j];
        acc[4 * j + 0] = v.x; acc[4 * j + 1] = v.y; acc[4 * j + 2] = v.z; acc[4 * j + 3] = v.w;
    }

    int s = rowptr[warp], e = rowptr[warp + 1];
    int k = s;
    for (; k + 3 < e; k += 4) {
        int u0 = col[k], u1 = col[k + 1], u2 = col[k + 2], u3 = col[k + 3];
        const float4* p0 = (const float4*)(hs + (size_t)u0 * ldh + lane * F);
        const float4* p1 = (const float4*)(hs + (size_t)u1 * ldh + lane * F);
        const float4* p2 = (const float4*)(hs + (size_t)u2 * ldh + lane * F);
        const float4* p3 = (const float4*)(hs + (size_t)u3 * ldh + lane * F);
        #pragma unroll
        for (int j = 0; j < V; j++) {
            float4 a = p0[j], b = p1[j], c = p2[j], d = p3[j];
            acc[4 * j + 0] += (a.x + b.x) + (c.x + d.x);
            acc[4 * j + 1] += (a.y + b.y) + (c.y + d.y);
            acc[4 * j + 2] += (a.z + b.z) + (c.z + d.z);
            acc[4 * j + 3] += (a.w + b.w) + (c.w + d.w);
        }
    }
    for (; k < e; k++) {
        int u = col[k];
        const float4* p = (const float4*)(hs + (size_t)u * ldh + lane * F);
        #pragma unroll
        for (int j = 0; j < V; j++) {
            float4 a = p[j];
            acc[4 * j + 0] += a.x; acc[4 * j + 1] += a.y;
            acc[4 * j + 2] += a.z; acc[4 * j + 3] += a.w;
        }
    }

    float dv = dinv[warp];
    float* orow = out + (size_t)warp * C + lane * F;
    const float* rrow = HASRES ? (res + (size_t)warp * ldh + lane * F) : nullptr;
    #pragma unroll
    for (int j = 0; j < F; j++) {
        float v = dv * acc[j] + bias[lane * F + j];
        if (HASRES) v += rrow[j] + rbias[lane * F + j];
        orow[j] = tf32r(fmaxf(v, 0.f));
    }
}

// ---------------- softmax * x3, per-graph pooled mean (no atomics) -------------
__device__ __forceinline__ int lowerb(const int* a, int n, int key) {
    int lo = 0, hi = n;
    while (lo < hi) { int mid = (lo + hi) >> 1; if (a[mid] < key) lo = mid + 1; else hi = mid; }
    return lo;
}

__global__ void softmax_pool_kernel(const float* __restrict__ logits, const float* __restrict__ x3,
                                    const int* __restrict__ batch,
                                    float* __restrict__ pooled, int n)
{
    __shared__ float sred[8 * 256];
    int g = blockIdx.x;
    int lane = threadIdx.x & 31;
    int w = threadIdx.x >> 5;

    int start = lowerb(batch, n, g);
    int end   = lowerb(batch, n, g + 1);

    float acc[8];
    #pragma unroll
    for (int j = 0; j < 8; j++) acc[j] = 0.f;

    for (int node = start + w; node < end; node += 8) {
        const float4* lr = (const float4*)(logits + (size_t)node * 256 + lane * 8);
        float4 a0 = lr[0], a1 = lr[1];
        float a[8] = {a0.x, a0.y, a0.z, a0.w, a1.x, a1.y, a1.z, a1.w};
        float m = a[0];
        #pragma unroll
        for (int j = 1; j < 8; j++) m = fmaxf(m, a[j]);
        #pragma unroll
        for (int off = 16; off > 0; off >>= 1) m = fmaxf(m, __shfl_xor_sync(0xFFFFFFFFu, m, off));
        float s = 0.f;
        #pragma unroll
        for (int j = 0; j < 8; j++) { a[j] = __expf(a[j] - m); s += a[j]; }
        #pragma unroll
        for (int off = 16; off > 0; off >>= 1) s += __shfl_xor_sync(0xFFFFFFFFu, s, off);
        float inv = 1.f / s;
        const float4* xr = (const float4*)(x3 + (size_t)node * 256 + lane * 8);
        float4 x0 = xr[0], x1 = xr[1];
        float xv[8] = {x0.x, x0.y, x0.z, x0.w, x1.x, x1.y, x1.z, x1.w};
        #pragma unroll
        for (int j = 0; j < 8; j++) acc[j] += a[j] * inv * xv[j];
    }

    #pragma unroll
    for (int j = 0; j < 8; j++) sred[w * 256 + lane * 8 + j] = acc[j];
    __syncthreads();

    int t = threadIdx.x;
    float v = 0.f;
    #pragma unroll
    for (int ww = 0; ww < 8; ww++) v += sred[ww * 256 + t];
    float invc = 1.f / fmaxf((float)(end - start), 1.f);
    pooled[(size_t)g * 256 + t] = v * invc;
}

// ---------------- final: (pooled + relu(fp+bfp) + relu(fg+bfg)) @ Wfc + bfc ----
__global__ void final_kernel(const float* __restrict__ pooled,
                             const float* __restrict__ fpa, const float* __restrict__ fga,
                             const float* __restrict__ bfp, const float* __restrict__ bfg,
                             const float* __restrict__ Wfc, const float* __restrict__ bfc,
                             float* __restrict__ out, int B)
{
    int warp = (blockIdx.x * blockDim.x + threadIdx.x) >> 5;
    if (warp >= B) return;
    int lane = threadIdx.x & 31;
    float s = 0.f;
    #pragma unroll
    for (int j = 0; j < 8; j++) {
        int idx = lane * 8 + j;
        size_t o = (size_t)warp * 256 + idx;
        float v = pooled[o]
                + fmaxf(fpa[o] + bfp[idx], 0.f)
                + fmaxf(fga[o] + bfg[idx], 0.f);
        s += v * Wfc[idx];
    }
    #pragma unroll
    for (int off = 16; off > 0; off >>= 1) s += __shfl_xor_sync(0xFFFFFFFFu, s, off);
    if (lane == 0) out[warp] = s + bfc[0];
}

// ---------------- host launcher -------------------------------------------------
extern "C" void kernel_launch(void* const* d_in, const int* in_sizes, int n_in,
                              void* d_out, int out_size)
{
    const float* x    = (const float*)d_in[0];
    const void*  eraw = d_in[1];
    const void*  braw = d_in[2];
    const float* fpf  = (const float*)d_in[3];
    const float* fgf  = (const float*)d_in[4];
    const float* W1   = (const float*)d_in[5];  const float* b1  = (const float*)d_in[6];
    const float* W2   = (const float*)d_in[7];  const float* b2  = (const float*)d_in[8];
    const float* W3   = (const float*)d_in[9];  const float* b3  = (const float*)d_in[10];
    const float* Wr1  = (const float*)d_in[11]; const float* br1 = (const float*)d_in[12];
    const float* Wr2  = (const float*)d_in[13]; const float* br2 = (const float*)d_in[14];
    const float* Wfp  = (const float*)d_in[15]; const float* bfp = (const float*)d_in[16];
    const float* Wfg  = (const float*)d_in[17]; const float* bfg = (const float*)d_in[18];
    const float* attn_W = (const float*)d_in[19];
    const float* Wfc  = (const float*)d_in[20]; const float* bfc = (const float*)d_in[21];
    float* out = (float*)d_out;

    int N = in_sizes[0] / 64;
    int E = in_sizes[1] / 2;
    int B = in_sizes[3] / 2048;

    float *work, *x1, *x2, *x3, *xr, *dinv, *pooled, *fp, *fg;
    float *wc1, *wc2, *wc3, *wattn;
    int *eidx, *batch, *deg, *rowptr, *cur, *col, *flag;
    cudaGetSymbolAddress((void**)&eidx,   g_eidx);
    cudaGetSymbolAddress((void**)&batch,  g_batch);
    cudaGetSymbolAddress((void**)&deg,    g_deg);
    cudaGetSymbolAddress((void**)&rowptr, g_rowptr);
    cudaGetSymbolAddress((void**)&cur,    g_cur);
    cudaGetSymbolAddress((void**)&col,    g_col);
    cudaGetSymbolAddress((void**)&flag,   g_flag);
    cudaGetSymbolAddress((void**)&dinv,   g_dinv);
    cudaGetSymbolAddress((void**)&work,   g_work);
    cudaGetSymbolAddress((void**)&x1,     g_x1);
    cudaGetSymbolAddress((void**)&x2,     g_x2);
    cudaGetSymbolAddress((void**)&x3,     g_x3);
    cudaGetSymbolAddress((void**)&xr,     g_xr);
    cudaGetSymbolAddress((void**)&wc1,    g_wc1);
    cudaGetSymbolAddress((void**)&wc2,    g_wc2);
    cudaGetSymbolAddress((void**)&wc3,    g_wc3);
    cudaGetSymbolAddress((void**)&wattn,  g_wattn);
    cudaGetSymbolAddress((void**)&pooled, g_pool);
    cudaGetSymbolAddress((void**)&fp,     g_fp);
    cudaGetSymbolAddress((void**)&fg,     g_fg);

    cudaMemsetAsync(deg, 0, N * sizeof(int));
    cudaMemsetAsync(cur, 0, N * sizeof(int));
    cudaMemsetAsync(fp,  0, (size_t)B * 256 * sizeof(float));
    cudaMemsetAsync(fg,  0, (size_t)B * 256 * sizeof(float));

    // dtype detect + index conversion (deg fused into edge conversion)
    detect_kernel<<<1, 32>>>((const unsigned int*)eraw, flag);
    cvt_edges_kernel<<<(E + 255) / 256, 256>>>(eraw, E, flag, eidx, deg);
    cvt_idx_kernel<<<(N + 255) / 256, 256>>>(braw, N, flag, batch);
    const int* srcA = eidx;
    const int* dstA = eidx + E;

    // tf32 pre-rounding of GEMM inputs (weights + x)
    round_tf32_kernel<<<(N * 64 + 255) / 256, 256>>>(x, xr, N * 64);
    round_tf32_kernel<<<(64 * 128 + 255) / 256, 256>>>(W1, wc1, 64 * 128);
    concat2_tf32_kernel<<<(128 * 512 + 255) / 256, 256>>>(W2, Wr1, wc2, 128);
    concat2_tf32_kernel<<<(256 * 512 + 255) / 256, 256>>>(W3, Wr2, wc3, 256);
    round_tf32_kernel<<<(256 * 256 + 255) / 256, 256>>>(attn_W, wattn, 256 * 256);

    // dinv / CSR
    dinv_kernel<<<(N + 255) / 256, 256>>>(deg, dinv, N);
    scan_kernel<<<1, 1024>>>(deg, rowptr, N);
    fill_csr_kernel<<<(E + 255) / 256, 256>>>(srcA, dstA, E, rowptr, cur, col);

    int aggBlocks = (N * 32 + 255) / 256;
    int gy = (N + 127) / 128;

    // Layer 1: work[:,0:128] = (xr @ wc1) * dinv ; x1 = relu(agg + b1)
    gemm_pipe_kernel<<<dim3(1, gy), 256>>>(xr, wc1, work, N, 128, 64, 512, dinv, 128);
    aggregate_kernel<128, false><<<aggBlocks, 256>>>(work, nullptr, 512, rowptr, col, dinv, b1, nullptr, x1, N);

    // Layer 2: work = x1 @ [W2|Wr1]; cols 0-255 scaled by dinv
    gemm_pipe_kernel<<<dim3(4, gy), 256>>>(x1, wc2, work, N, 512, 128, 512, dinv, 256);
    aggregate_kernel<256, true><<<aggBlocks, 256>>>(work, work + 256, 512, rowptr, col, dinv, b2, br1, x2, N);

    // Layer 3
    gemm_pipe_kernel<<<dim3(4, gy), 256>>>(x2, wc3, work, N, 512, 256, 512, dinv, 256);
    aggregate_kernel<256, true><<<aggBlocks, 256>>>(work, work + 256, 512, rowptr, col, dinv, b3, br2, x3, N);

    // Attention logits into work (compact stride 256)
    gemm_pipe_kernel<<<dim3(2, gy), 256>>>(x3, wattn, work, N, 256, 256, 256, nullptr, 0);

    // fp: split-K atomic accumulate; fg: single chunk (legacy kernel handles K tails)
    gemm_tc_kernel<<<dim3(2, (B + 127) / 128, 8), 256>>>(fpf, Wfp, fp, B, 256, 2048, 256, 1);
    gemm_tc_kernel<<<dim3(2, (B + 127) / 128, 1), 256>>>(fgf, Wfg, fg, B, 256, 167, 167, 1);

    // softmax * x3 -> per-graph pooled mean
    softmax_pool_kernel<<<B, 256>>>(work, x3, batch, pooled, N);

    // final projection
    final_kernel<<<(B * 32 + 255) / 256, 256>>>(pooled, fp, fg, bfp, bfg, Wfc, bfc, out, B);
}

// round 5
// speedup vs baseline: 1.7930x; 1.0850x over previous
#include <cuda_runtime.h>
#include <cstdint>
#include <mma.h>
#include <math.h>

using namespace nvcuda;

#define NODES_MAX 50000
#define EDGES_MAX 800000
#define GRAPHS_MAX 1024

// ---------------- scratch (device globals) ------------------------------------
__device__ int   g_eidx[2 * EDGES_MAX];
__device__ int   g_batch[NODES_MAX];
__device__ int   g_deg[NODES_MAX];
__device__ int   g_rowptr[NODES_MAX + 1];
__device__ int   g_cur[NODES_MAX];
__device__ int   g_col[EDGES_MAX];
__device__ int   g_flag[1];
__device__ float g_dinv[NODES_MAX];
__device__ float g_xs0[(size_t)NODES_MAX * 64];
__device__ float g_A1 [(size_t)NODES_MAX * 64];
__device__ float g_A2 [(size_t)NODES_MAX * 256];   // [z2 | x1]
__device__ float g_xs1[(size_t)NODES_MAX * 128];
__device__ float g_A3 [(size_t)NODES_MAX * 512];   // [z3 | x2]
__device__ float g_xs2[(size_t)NODES_MAX * 256];
__device__ float g_x3 [(size_t)NODES_MAX * 256];
__device__ float g_work[(size_t)NODES_MAX * 256];  // attn logits
__device__ float g_w1r[64 * 128];
__device__ float g_w2s[256 * 256];                 // [W2 ; Wr1]
__device__ float g_w3s[512 * 256];                 // [W3 ; Wr2]
__device__ float g_wattn[256 * 256];
__device__ float g_pool[GRAPHS_MAX * 256];
__device__ float g_fp[GRAPHS_MAX * 256];
__device__ float g_fg[GRAPHS_MAX * 256];

__device__ __forceinline__ float tf32r(float x) {
    float r;
    asm("cvt.rna.tf32.f32 %0, %1;" : "=f"(r) : "f"(x));
    return r;
}

__device__ __forceinline__ void cp16(uint32_t dst, const void* src, bool pred) {
    int bytes = pred ? 16 : 0;
    asm volatile("cp.async.cg.shared.global [%0], [%1], 16, %2;\n"
                 :: "r"(dst), "l"(src), "r"(bytes));
}
__device__ __forceinline__ void cp_commit() { asm volatile("cp.async.commit_group;\n"); }
__device__ __forceinline__ void cp_wait0()  { asm volatile("cp.async.wait_group 0;\n"); }

// ---------------- dtype detect + index convert --------------------------------
__global__ void detect_kernel(const unsigned int* __restrict__ w, int* __restrict__ flag) {
    int t = threadIdx.x;
    unsigned int v = w[2 * t + 1] | w[2 * (t + 32) + 1] | w[2 * (t + 64) + 1] | w[2 * (t + 96) + 1];
    unsigned int nz = __ballot_sync(0xFFFFFFFFu, v != 0u);
    if (t == 0) *flag = (nz == 0u) ? 1 : 0;
}

__global__ void cvt_edges_kernel(const void* __restrict__ raw, int E,
                                 const int* __restrict__ flag, int* __restrict__ eidx,
                                 int* __restrict__ deg) {
    int i = blockIdx.x * blockDim.x + threadIdx.x;
    if (i >= E) return;
    int s, d;
    if (*flag) {
        s = (int)((const long long*)raw)[i];
        d = (int)((const long long*)raw)[E + i];
    } else {
        s = ((const int*)raw)[i];
        d = ((const int*)raw)[E + i];
    }
    eidx[i] = s;
    eidx[E + i] = d;
    atomicAdd(&deg[d], 1);
}

__global__ void cvt_idx_kernel(const void* __restrict__ raw, int n,
                               const int* __restrict__ flag, int* __restrict__ out) {
    int i = blockIdx.x * blockDim.x + threadIdx.x;
    if (i >= n) return;
    if (*flag) out[i] = (int)((const long long*)raw)[i];
    else       out[i] = ((const int*)raw)[i];
}

// ---------------- prep kernels --------------------------------------------------
__global__ void dinv_kernel(const int* __restrict__ deg, float* __restrict__ dinv, int n) {
    int i = blockIdx.x * blockDim.x + threadIdx.x;
    if (i < n) dinv[i] = rsqrtf((float)deg[i] + 1.0f);
}

// xs0 = dinv (row) * x
__global__ void scale0_kernel(const float* __restrict__ x, const float* __restrict__ dinv,
                              float* __restrict__ xs, int total) {
    int i = blockIdx.x * blockDim.x + threadIdx.x;
    if (i < total) xs[i] = x[i] * dinv[i >> 6];
}

__global__ void round_tf32_kernel(const float* __restrict__ in, float* __restrict__ out, int n) {
    int i = blockIdx.x * blockDim.x + threadIdx.x;
    if (i < n) out[i] = tf32r(in[i]);
}

// stack rows: out rows [0,K1) = B1, rows [K1, K1+K2) = B2; width 256
__global__ void stack_tf32_kernel(const float* __restrict__ B1, const float* __restrict__ B2,
                                  float* __restrict__ out, int K1, int Ktot) {
    int i = blockIdx.x * blockDim.x + threadIdx.x;
    if (i >= Ktot * 256) return;
    int k = i >> 8, c = i & 255;
    float v = (k < K1) ? B1[k * 256 + c] : B2[(k - K1) * 256 + c];
    out[i] = tf32r(v);
}

__global__ void scan_kernel(const int* __restrict__ deg, int* __restrict__ rowptr, int n) {
    __shared__ int sums[1024];
    int t = threadIdx.x;
    int chunk = (n + 1023) / 1024;
    int s = t * chunk;
    int e = min(s + chunk, n);
    int acc = 0;
    for (int i = s; i < e; i++) acc += deg[i];
    sums[t] = acc;
    __syncthreads();
    for (int d = 1; d < 1024; d <<= 1) {
        int v = (t >= d) ? sums[t - d] : 0;
        __syncthreads();
        sums[t] += v;
        __syncthreads();
    }
    int off = (t == 0) ? 0 : sums[t - 1];
    for (int i = s; i < e; i++) { rowptr[i] = off; off += deg[i]; }
    if (t == 1023) rowptr[n] = sums[1023];
}

__global__ void fill_csr_kernel(const int* __restrict__ src, const int* __restrict__ dst, int E,
                                const int* __restrict__ rowptr, int* __restrict__ cur,
                                int* __restrict__ col) {
    int i = blockIdx.x * blockDim.x + threadIdx.x;
    if (i >= E) return;
    int d = dst[i];
    int pos = rowptr[d] + atomicAdd(&cur[d], 1);
    col[pos] = src[i];
}

// ---------------- input-space aggregation --------------------------------------
// out[v, lane*F + j] = tf32r( dinv[v] * ( xs[v] + sum_{u in N(v)} xs[u] )[j] )
template <int C>
__global__ void aggregate_kernel(const float* __restrict__ xs,
                                 const int* __restrict__ rowptr, const int* __restrict__ col,
                                 const float* __restrict__ dinv,
                                 float* __restrict__ out, int ldo, int n)
{
    int node = (blockIdx.x * blockDim.x + threadIdx.x) >> 5;
    if (node >= n) return;
    int lane = threadIdx.x & 31;
    constexpr int F = C / 32;

    float acc[F];
    if constexpr (F == 2) {
        float2 v = *(const float2*)(xs + (size_t)node * C + lane * 2);
        acc[0] = v.x; acc[1] = v.y;
    } else {
        #pragma unroll
        for (int j = 0; j < F / 4; j++) {
            float4 v = ((const float4*)(xs + (size_t)node * C + lane * F))[j];
            acc[4 * j + 0] = v.x; acc[4 * j + 1] = v.y;
            acc[4 * j + 2] = v.z; acc[4 * j + 3] = v.w;
        }
    }

    int s = rowptr[node], e = rowptr[node + 1];
    int k = s;
    for (; k + 3 < e; k += 4) {
        int u0 = col[k], u1 = col[k + 1], u2 = col[k + 2], u3 = col[k + 3];
        const float* p0 = xs + (size_t)u0 * C + lane * F;
        const float* p1 = xs + (size_t)u1 * C + lane * F;
        const float* p2 = xs + (size_t)u2 * C + lane * F;
        const float* p3 = xs + (size_t)u3 * C + lane * F;
        if constexpr (F == 2) {
            float2 a = *(const float2*)p0, b = *(const float2*)p1;
            float2 c = *(const float2*)p2, d = *(const float2*)p3;
            acc[0] += (a.x + b.x) + (c.x + d.x);
            acc[1] += (a.y + b.y) + (c.y + d.y);
        } else {
            #pragma unroll
            for (int j = 0; j < F / 4; j++) {
                float4 a = ((const float4*)p0)[j], b = ((const float4*)p1)[j];
                float4 c = ((const float4*)p2)[j], d = ((const float4*)p3)[j];
                acc[4 * j + 0] += (a.x + b.x) + (c.x + d.x);
                acc[4 * j + 1] += (a.y + b.y) + (c.y + d.y);
                acc[4 * j + 2] += (a.z + b.z) + (c.z + d.z);
                acc[4 * j + 3] += (a.w + b.w) + (c.w + d.w);
            }
        }
    }
    for (; k < e; k++) {
        const float* p = xs + (size_t)col[k] * C + lane * F;
        if constexpr (F == 2) {
            float2 a = *(const float2*)p;
            acc[0] += a.x; acc[1] += a.y;
        } else {
            #pragma unroll
            for (int j = 0; j < F / 4; j++) {
                float4 a = ((const float4*)p)[j];
                acc[4 * j + 0] += a.x; acc[4 * j + 1] += a.y;
                acc[4 * j + 2] += a.z; acc[4 * j + 3] += a.w;
            }
        }
    }

    float dv = dinv[node];
    float* orow = out + (size_t)node * ldo + lane * F;
    #pragma unroll
    for (int j = 0; j < F; j++) orow[j] = tf32r(dv * acc[j]);
}

// ---------------- pipelined tf32 GEMM (inputs pre-rounded) ----------------------
// C = A[MxK] @ B[KxN]; row stride of A == K; K%16==0; N%128==0.
// Epilogue: v = acc (+bias1[c]) (+bias2[c]); if reluRound: v = tf32r(max(v,0));
// C[r*ldc+c] = v; if C2: C2[r*ld2+c] = dinv[r]*v.
__global__ __launch_bounds__(256, 2) void gemm_pipe_kernel(
    const float* __restrict__ A, const float* __restrict__ B, float* __restrict__ C,
    int M, int N, int K, int ldc,
    const float* __restrict__ bias1, const float* __restrict__ bias2, int reluRound,
    float* __restrict__ C2, int ld2, const float* __restrict__ dinv)
{
    const int BM = 128, BK = 16;
    const int LDA = 20, LDB = 132;
    __shared__ __align__(16) float As[2][BM * LDA];
    __shared__ __align__(16) float Bs[2][BK * LDB];

    int tid  = threadIdx.x;
    int lane = tid & 31;
    int warp = tid >> 5;
    int warpM = (warp >> 2) * 64;
    int warpN = (warp & 3) * 32;
    int rowBase = blockIdx.y * BM;
    int colBase = blockIdx.x * 128;

    wmma::fragment<wmma::accumulator, 16, 16, 8, float> acc[4][2];
    #pragma unroll
    for (int m = 0; m < 4; m++)
        #pragma unroll
        for (int n = 0; n < 2; n++) wmma::fill_fragment(acc[m][n], 0.0f);

    int ntiles = K / BK;

    uint32_t asBase[2], bsBase[2];
    asBase[0] = (uint32_t)__cvta_generic_to_shared(&As[0][0]);
    asBase[1] = (uint32_t)__cvta_generic_to_shared(&As[1][0]);
    bsBase[0] = (uint32_t)__cvta_generic_to_shared(&Bs[0][0]);
    bsBase[1] = (uint32_t)__cvta_generic_to_shared(&Bs[1][0]);

    auto issue = [&](int t, int s) {
        int k0 = t * BK;
        #pragma unroll
        for (int h = 0; h < 2; h++) {
            int c = tid + h * 256;
            int row = c >> 2, q = c & 3;
            int r = rowBase + row;
            bool ok = (r < M);
            const float* src = A + (size_t)(ok ? r : 0) * K + k0 + q * 4;
            cp16(asBase[s] + (uint32_t)(row * LDA + q * 4) * 4u, src, ok);
        }
        #pragma unroll
        for (int h = 0; h < 2; h++) {
            int c = tid + h * 256;
            int row = c >> 5, q = c & 31;
            const float* src = B + (size_t)(k0 + row) * N + colBase + q * 4;
            cp16(bsBase[s] + (uint32_t)(row * LDB + q * 4) * 4u, src, true);
        }
    };

    issue(0, 0);
    cp_commit();

    for (int t = 0; t < ntiles; t++) {
        cp_wait0();
        __syncthreads();
        if (t + 1 < ntiles) { issue(t + 1, (t + 1) & 1); cp_commit(); }

        const float* as = As[t & 1];
        const float* bs = Bs[t & 1];
        #pragma unroll
        for (int kk = 0; kk < BK; kk += 8) {
            wmma::fragment<wmma::matrix_a, 16, 16, 8, wmma::precision::tf32, wmma::row_major> af[4];
            wmma::fragment<wmma::matrix_b, 16, 16, 8, wmma::precision::tf32, wmma::row_major> bf[2];
            #pragma unroll
            for (int m = 0; m < 4; m++)
                wmma::load_matrix_sync(af[m], as + (warpM + 16 * m) * LDA + kk, LDA);
            #pragma unroll
            for (int n = 0; n < 2; n++)
                wmma::load_matrix_sync(bf[n], bs + kk * LDB + warpN + 16 * n, LDB);
            #pragma unroll
            for (int m = 0; m < 4; m++)
                #pragma unroll
                for (int n = 0; n < 2; n++)
                    wmma::mma_sync(acc[m][n], af[m], bf[n], acc[m][n]);
        }
    }
    __syncthreads();

    // epilogue via smem staging
    float* es = &As[0][0] + warp * 320;
    #pragma unroll
    for (int m = 0; m < 4; m++) {
        #pragma unroll
        for (int n = 0; n < 2; n++) {
            wmma::store_matrix_sync(es, acc[m][n], 20, wmma::mem_row_major);
            __syncwarp();
            #pragma unroll
            for (int i = 0; i < 2; i++) {
                int r  = i * 8 + (lane >> 2);
                int c4 = (lane & 3) * 4;
                int gr = rowBase + warpM + 16 * m + r;
                int gc = colBase + warpN + 16 * n + c4;
                if (gr < M) {
                    float4 v = *(float4*)(es + r * 20 + c4);
                    if (bias1) {
                        v.x += bias1[gc]; v.y += bias1[gc + 1];
                        v.z += bias1[gc + 2]; v.w += bias1[gc + 3];
                    }
                    if (bias2) {
                        v.x += bias2[gc]; v.y += bias2[gc + 1];
                        v.z += bias2[gc + 2]; v.w += bias2[gc + 3];
                    }
                    if (reluRound) {
                        v.x = tf32r(fmaxf(v.x, 0.f)); v.y = tf32r(fmaxf(v.y, 0.f));
                        v.z = tf32r(fmaxf(v.z, 0.f)); v.w = tf32r(fmaxf(v.w, 0.f));
                    }
                    *(float4*)(C + (size_t)gr * ldc + gc) = v;
                    if (C2) {
                        float dv = dinv[gr];
                        float4 w2 = make_float4(v.x * dv, v.y * dv, v.z * dv, v.w * dv);
                        *(float4*)(C2 + (size_t)gr * ld2 + gc) = w2;
                    }
                }
            }
            __syncwarp();
        }
    }
}

// ---------------- legacy tf32 GEMM (K tails / atomics) for fp/fg ---------------
__global__ __launch_bounds__(256, 2) void gemm_tc_kernel(
    const float* __restrict__ A, const float* __restrict__ B, float* __restrict__ C,
    int M, int N, int K, int kChunk, int atomicOut)
{
    const int BM = 128, BN = 128, BK = 16;
    const int LDA = 20, LDB = 132;
    __shared__ __align__(16) float As[BM * LDA];
    __shared__ __align__(16) float Bs[BK * LDB];

    int tid  = threadIdx.x;
    int lane = tid & 31;
    int warp = tid >> 5;
    int warpM = (warp >> 2) * 64;
    int warpN = (warp & 3) * 32;

    int rowBase = blockIdx.y * BM;
    int colBase = blockIdx.x * BN;
    int kStart  = blockIdx.z * kChunk;
    int kEnd    = min(K, kStart + kChunk);

    wmma::fragment<wmma::accumulator, 16, 16, 8, float> acc[4][2];
    #pragma unroll
    for (int m = 0; m < 4; m++)
        #pragma unroll
        for (int n = 0; n < 2; n++) wmma::fill_fragment(acc[m][n], 0.0f);

    bool kAligned = ((K & 3) == 0);
    int aRow = tid >> 1, aCol = (tid & 1) * 8;
    int bRow = tid >> 4, bCol = (tid & 15) * 8;

    for (int k0 = kStart; k0 < kEnd; k0 += BK) {
        {
            int r = rowBase + aRow;
            #pragma unroll
            for (int j = 0; j < 2; j++) {
                int cb = k0 + aCol + j * 4;
                float4 v = make_float4(0.f, 0.f, 0.f, 0.f);
                if (r < M) {
                    if (kAligned && (cb + 3 < kEnd)) {
                        v = *(const float4*)(A + (size_t)r * K + cb);
                    } else {
                        if (cb + 0 < kEnd) v.x = A[(size_t)r * K + cb + 0];
                        if (cb + 1 < kEnd) v.y = A[(size_t)r * K + cb + 1];
                        if (cb + 2 < kEnd) v.z = A[(size_t)r * K + cb + 2];
                        if (cb + 3 < kEnd) v.w = A[(size_t)r * K + cb + 3];
                    }
                }
                float* dstp = As + aRow * LDA + aCol + j * 4;
                dstp[0] = tf32r(v.x); dstp[1] = tf32r(v.y);
                dstp[2] = tf32r(v.z); dstp[3] = tf32r(v.w);
            }
        }
        {
            int kr = k0 + bRow;
            #pragma unroll
            for (int j = 0; j < 2; j++) {
                float4 v = make_float4(0.f, 0.f, 0.f, 0.f);
                if (kr < kEnd) v = *(const float4*)(B + (size_t)kr * N + colBase + bCol + j * 4);
                float* dstp = Bs + bRow * LDB + bCol + j * 4;
                dstp[0] = tf32r(v.x); dstp[1] = tf32r(v.y);
                dstp[2] = tf32r(v.z); dstp[3] = tf32r(v.w);
            }
        }
        __syncthreads();

        #pragma unroll
        for (int kk = 0; kk < BK; kk += 8) {
            wmma::fragment<wmma::matrix_a, 16, 16, 8, wmma::precision::tf32, wmma::row_major> af[4];
            wmma::fragment<wmma::matrix_b, 16, 16, 8, wmma::precision::tf32, wmma::row_major> bf[2];
            #pragma unroll
            for (int m = 0; m < 4; m++)
                wmma::load_matrix_sync(af[m], As + (warpM + 16 * m) * LDA + kk, LDA);
            #pragma unroll
            for (int n = 0; n < 2; n++)
                wmma::load_matrix_sync(bf[n], Bs + kk * LDB + warpN + 16 * n, LDB);
            #pragma unroll
            for (int m = 0; m < 4; m++)
                #pragma unroll
                for (int n = 0; n < 2; n++)
                    wmma::mma_sync(acc[m][n], af[m], bf[n], acc[m][n]);
        }
        __syncthreads();
    }

    float* es = As + warp * 320;
    #pragma unroll
    for (int m = 0; m < 4; m++) {
        #pragma unroll
        for (int n = 0; n < 2; n++) {
            wmma::store_matrix_sync(es, acc[m][n], 20, wmma::mem_row_major);
            __syncwarp();
            #pragma unroll
            for (int i = 0; i < 2; i++) {
                int r  = i * 8 + (lane >> 2);
                int c4 = (lane & 3) * 4;
                int gr = rowBase + warpM + 16 * m + r;
                int gc = colBase + warpN + 16 * n + c4;
                if (gr < M) {
                    float4 v = *(float4*)(es + r * 20 + c4);
                    float* cp = C + (size_t)gr * N + gc;
                    if (atomicOut) {
                        atomicAdd(cp + 0, v.x); atomicAdd(cp + 1, v.y);
                        atomicAdd(cp + 2, v.z); atomicAdd(cp + 3, v.w);
                    } else {
                        *(float4*)cp = v;
                    }
                }
            }
            __syncwarp();
        }
    }
}

// ---------------- softmax * x3, per-graph pooled mean ---------------------------
__device__ __forceinline__ int lowerb(const int* a, int n, int key) {
    int lo = 0, hi = n;
    while (lo < hi) { int mid = (lo + hi) >> 1; if (a[mid] < key) lo = mid + 1; else hi = mid; }
    return lo;
}

__global__ void softmax_pool_kernel(const float* __restrict__ logits, const float* __restrict__ x3,
                                    const int* __restrict__ batch,
                                    float* __restrict__ pooled, int n)
{
    __shared__ float sred[8 * 256];
    int g = blockIdx.x;
    int lane = threadIdx.x & 31;
    int w = threadIdx.x >> 5;

    int start = lowerb(batch, n, g);
    int end   = lowerb(batch, n, g + 1);

    float acc[8];
    #pragma unroll
    for (int j = 0; j < 8; j++) acc[j] = 0.f;

    for (int node = start + w; node < end; node += 8) {
        const float4* lr = (const float4*)(logits + (size_t)node * 256 + lane * 8);
        float4 a0 = lr[0], a1 = lr[1];
        float a[8] = {a0.x, a0.y, a0.z, a0.w, a1.x, a1.y, a1.z, a1.w};
        float m = a[0];
        #pragma unroll
        for (int j = 1; j < 8; j++) m = fmaxf(m, a[j]);
        #pragma unroll
        for (int off = 16; off > 0; off >>= 1) m = fmaxf(m, __shfl_xor_sync(0xFFFFFFFFu, m, off));
        float s = 0.f;
        #pragma unroll
        for (int j = 0; j < 8; j++) { a[j] = __expf(a[j] - m); s += a[j]; }
        #pragma unroll
        for (int off = 16; off > 0; off >>= 1) s += __shfl_xor_sync(0xFFFFFFFFu, s, off);
        float inv = 1.f / s;
        const float4* xr = (const float4*)(x3 + (size_t)node * 256 + lane * 8);
        float4 x0 = xr[0], x1 = xr[1];
        float xv[8] = {x0.x, x0.y, x0.z, x0.w, x1.x, x1.y, x1.z, x1.w};
        #pragma unroll
        for (int j = 0; j < 8; j++) acc[j] += a[j] * inv * xv[j];
    }

    #pragma unroll
    for (int j = 0; j < 8; j++) sred[w * 256 + lane * 8 + j] = acc[j];
    __syncthreads();

    int t = threadIdx.x;
    float v = 0.f;
    #pragma unroll
    for (int ww = 0; ww < 8; ww++) v += sred[ww * 256 + t];
    float invc = 1.f / fmaxf((float)(end - start), 1.f);
    pooled[(size_t)g * 256 + t] = v * invc;
}

// ---------------- final ---------------------------------------------------------
__global__ void final_kernel(const float* __restrict__ pooled,
                             const float* __restrict__ fpa, const float* __restrict__ fga,
                             const float* __restrict__ bfp, const float* __restrict__ bfg,
                             const float* __restrict__ Wfc, const float* __restrict__ bfc,
                             float* __restrict__ out, int B)
{
    int warp = (blockIdx.x * blockDim.x + threadIdx.x) >> 5;
    if (warp >= B) return;
    int lane = threadIdx.x & 31;
    float s = 0.f;
    #pragma unroll
    for (int j = 0; j < 8; j++) {
        int idx = lane * 8 + j;
        size_t o = (size_t)warp * 256 + idx;
        float v = pooled[o]
                + fmaxf(fpa[o] + bfp[idx], 0.f)
                + fmaxf(fga[o] + bfg[idx], 0.f);
        s += v * Wfc[idx];
    }
    #pragma unroll
    for (int off = 16; off > 0; off >>= 1) s += __shfl_xor_sync(0xFFFFFFFFu, s, off);
    if (lane == 0) out[warp] = s + bfc[0];
}

// ---------------- host launcher -------------------------------------------------
extern "C" void kernel_launch(void* const* d_in, const int* in_sizes, int n_in,
                              void* d_out, int out_size)
{
    const float* x    = (const float*)d_in[0];
    const void*  eraw = d_in[1];
    const void*  braw = d_in[2];
    const float* fpf  = (const float*)d_in[3];
    const float* fgf  = (const float*)d_in[4];
    const float* W1   = (const float*)d_in[5];  const float* b1  = (const float*)d_in[6];
    const float* W2   = (const float*)d_in[7];  const float* b2  = (const float*)d_in[8];
    const float* W3   = (const float*)d_in[9];  const float* b3  = (const float*)d_in[10];
    const float* Wr1  = (const float*)d_in[11]; const float* br1 = (const float*)d_in[12];
    const float* Wr2  = (const float*)d_in[13]; const float* br2 = (const float*)d_in[14];
    const float* Wfp  = (const float*)d_in[15]; const float* bfp = (const float*)d_in[16];
    const float* Wfg  = (const float*)d_in[17]; const float* bfg = (const float*)d_in[18];
    const float* attn_W = (const float*)d_in[19];
    const float* Wfc  = (const float*)d_in[20]; const float* bfc = (const float*)d_in[21];
    float* out = (float*)d_out;

    int N = in_sizes[0] / 64;
    int E = in_sizes[1] / 2;
    int B = in_sizes[3] / 2048;

    float *xs0, *A1, *A2, *xs1, *A3, *xs2, *x3, *work, *dinv, *pooled, *fp, *fg;
    float *w1r, *w2s, *w3s, *wattn;
    int *eidx, *batch, *deg, *rowptr, *cur, *col, *flag;
    cudaGetSymbolAddress((void**)&eidx,   g_eidx);
    cudaGetSymbolAddress((void**)&batch,  g_batch);
    cudaGetSymbolAddress((void**)&deg,    g_deg);
    cudaGetSymbolAddress((void**)&rowptr, g_rowptr);
    cudaGetSymbolAddress((void**)&cur,    g_cur);
    cudaGetSymbolAddress((void**)&col,    g_col);
    cudaGetSymbolAddress((void**)&flag,   g_flag);
    cudaGetSymbolAddress((void**)&dinv,   g_dinv);
    cudaGetSymbolAddress((void**)&xs0,    g_xs0);
    cudaGetSymbolAddress((void**)&A1,     g_A1);
    cudaGetSymbolAddress((void**)&A2,     g_A2);
    cudaGetSymbolAddress((void**)&xs1,    g_xs1);
    cudaGetSymbolAddress((void**)&A3,     g_A3);
    cudaGetSymbolAddress((void**)&xs2,    g_xs2);
    cudaGetSymbolAddress((void**)&x3,     g_x3);
    cudaGetSymbolAddress((void**)&work,   g_work);
    cudaGetSymbolAddress((void**)&w1r,    g_w1r);
    cudaGetSymbolAddress((void**)&w2s,    g_w2s);
    cudaGetSymbolAddress((void**)&w3s,    g_w3s);
    cudaGetSymbolAddress((void**)&wattn,  g_wattn);
    cudaGetSymbolAddress((void**)&pooled, g_pool);
    cudaGetSymbolAddress((void**)&fp,     g_fp);
    cudaGetSymbolAddress((void**)&fg,     g_fg);

    cudaMemsetAsync(deg, 0, N * sizeof(int));
    cudaMemsetAsync(cur, 0, N * sizeof(int));
    cudaMemsetAsync(fp,  0, (size_t)B * 256 * sizeof(float));
    cudaMemsetAsync(fg,  0, (size_t)B * 256 * sizeof(float));

    // dtype detect + index conversion + degree
    detect_kernel<<<1, 32>>>((const unsigned int*)eraw, flag);
    cvt_edges_kernel<<<(E + 255) / 256, 256>>>(eraw, E, flag, eidx, deg);
    cvt_idx_kernel<<<(N + 255) / 256, 256>>>(braw, N, flag, batch);
    const int* srcA = eidx;
    const int* dstA = eidx + E;

    dinv_kernel<<<(N + 255) / 256, 256>>>(deg, dinv, N);
    scale0_kernel<<<(N * 64 + 255) / 256, 256>>>(x, dinv, xs0, N * 64);

    // weight prep (tf32-rounded, stacked)
    round_tf32_kernel<<<(64 * 128 + 255) / 256, 256>>>(W1, w1r, 64 * 128);
    stack_tf32_kernel<<<(256 * 256 + 255) / 256, 256>>>(W2, Wr1, w2s, 128, 256);
    stack_tf32_kernel<<<(512 * 256 + 255) / 256, 256>>>(W3, Wr2, w3s, 256, 512);
    round_tf32_kernel<<<(256 * 256 + 255) / 256, 256>>>(attn_W, wattn, 256 * 256);

    // CSR
    scan_kernel<<<1, 1024>>>(deg, rowptr, N);
    fill_csr_kernel<<<(E + 255) / 256, 256>>>(srcA, dstA, E, rowptr, cur, col);

    int aggBlocks = (N * 32 + 255) / 256;
    int gy = (N + 127) / 128;

    // Layer 1: z1 = agg(xs0); x1 = relu(z1@W1 + b1) -> A2 right half + xs1
    aggregate_kernel<64><<<aggBlocks, 256>>>(xs0, rowptr, col, dinv, A1, 64, N);
    gemm_pipe_kernel<<<dim3(1, gy), 256>>>(A1, w1r, A2 + 128, N, 128, 64, 256,
                                           b1, nullptr, 1, xs1, 128, dinv);

    // Layer 2: z2 = agg(xs1) -> A2 left; x2 = relu([z2|x1]@[W2;Wr1] + b2 + br1)
    aggregate_kernel<128><<<aggBlocks, 256>>>(xs1, rowptr, col, dinv, A2, 256, N);
    gemm_pipe_kernel<<<dim3(2, gy), 256>>>(A2, w2s, A3 + 256, N, 256, 256, 512,
                                           b2, br1, 1, xs2, 256, dinv);

    // Layer 3: z3 = agg(xs2) -> A3 left; x3 = relu([z3|x2]@[W3;Wr2] + b3 + br2)
    aggregate_kernel<256><<<aggBlocks, 256>>>(xs2, rowptr, col, dinv, A3, 512, N);
    gemm_pipe_kernel<<<dim3(2, gy), 256>>>(A3, w3s, x3, N, 256, 512, 256,
                                           b3, br2, 1, nullptr, 0, nullptr);

    // Attention logits
    gemm_pipe_kernel<<<dim3(2, gy), 256>>>(x3, wattn, work, N, 256, 256, 256,
                                           nullptr, nullptr, 0, nullptr, 0, nullptr);

    // fp / fg (legacy kernel, split-K atomics for fp)
    gemm_tc_kernel<<<dim3(2, (B + 127) / 128, 8), 256>>>(fpf, Wfp, fp, B, 256, 2048, 256, 1);
    gemm_tc_kernel<<<dim3(2, (B + 127) / 128, 1), 256>>>(fgf, Wfg, fg, B, 256, 167, 167, 1);

    // softmax * x3 -> per-graph pooled mean
    softmax_pool_kernel<<<B, 256>>>(work, x3, batch, pooled, N);

    // final projection
    final_kernel<<<(B * 32 + 255) / 256, 256>>>(pooled, fp, fg, bfp, bfg, Wfc, bfc, out, B);
}

// round 6
// speedup vs baseline: 3.3339x; 1.8594x over previous
#include <cuda_runtime.h>
#include <cuda_fp16.h>
#include <cstdint>
#include <mma.h>
#include <math.h>

using namespace nvcuda;

#define NODES_MAX 50000
#define EDGES_MAX 800000
#define GRAPHS_MAX 1024

// ---------------- scratch (device globals) ------------------------------------
__device__ int    g_eidx[2 * EDGES_MAX];
__device__ int    g_batch[NODES_MAX];
__device__ int    g_deg[NODES_MAX];
__device__ int    g_rowptr[NODES_MAX + 1];
__device__ int    g_cur[NODES_MAX];
__device__ int    g_col[EDGES_MAX];
__device__ int    g_flag[1];
__device__ float  g_dinv[NODES_MAX];
__device__ __half g_xs0[(size_t)NODES_MAX * 64];
__device__ __half g_A1 [(size_t)NODES_MAX * 64];
__device__ __half g_A2 [(size_t)NODES_MAX * 256];   // [z2 | x1]
__device__ __half g_xs1[(size_t)NODES_MAX * 128];
__device__ __half g_A3 [(size_t)NODES_MAX * 512];   // [z3 | x2]
__device__ __half g_xs2[(size_t)NODES_MAX * 256];
__device__ __half g_x3 [(size_t)NODES_MAX * 256];
__device__ float  g_work[(size_t)NODES_MAX * 256];  // attn logits (MUST be fp32)
__device__ __half g_w1r[64 * 128];
__device__ __half g_w2s[256 * 256];                 // [W2 ; Wr1]
__device__ __half g_w3s[512 * 256];                 // [W3 ; Wr2]
__device__ __half g_wattn[256 * 256];
__device__ float  g_pool[GRAPHS_MAX * 256];
__device__ float  g_fp[GRAPHS_MAX * 256];
__device__ float  g_fg[GRAPHS_MAX * 256];

__device__ __forceinline__ float tf32r(float x) {
    float r;
    asm("cvt.rna.tf32.f32 %0, %1;" : "=f"(r) : "f"(x));
    return r;
}

__device__ __forceinline__ void cp16(uint32_t dst, const void* src, bool pred) {
    int bytes = pred ? 16 : 0;
    asm volatile("cp.async.cg.shared.global [%0], [%1], 16, %2;\n"
                 :: "r"(dst), "l"(src), "r"(bytes));
}
__device__ __forceinline__ void cp_commit() { asm volatile("cp.async.commit_group;\n"); }
__device__ __forceinline__ void cp_wait0()  { asm volatile("cp.async.wait_group 0;\n"); }

// ---------------- dtype detect + index convert --------------------------------
__global__ void detect_kernel(const unsigned int* __restrict__ w, int* __restrict__ flag) {
    int t = threadIdx.x;
    unsigned int v = w[2 * t + 1] | w[2 * (t + 32) + 1] | w[2 * (t + 64) + 1] | w[2 * (t + 96) + 1];
    unsigned int nz = __ballot_sync(0xFFFFFFFFu, v != 0u);
    if (t == 0) *flag = (nz == 0u) ? 1 : 0;
}

__global__ void cvt_edges_kernel(const void* __restrict__ raw, int E,
                                 const int* __restrict__ flag, int* __restrict__ eidx,
                                 int* __restrict__ deg) {
    int i = blockIdx.x * blockDim.x + threadIdx.x;
    if (i >= E) return;
    int s, d;
    if (*flag) {
        s = (int)((const long long*)raw)[i];
        d = (int)((const long long*)raw)[E + i];
    } else {
        s = ((const int*)raw)[i];
        d = ((const int*)raw)[E + i];
    }
    eidx[i] = s;
    eidx[E + i] = d;
    atomicAdd(&deg[d], 1);
}

__global__ void cvt_idx_kernel(const void* __restrict__ raw, int n,
                               const int* __restrict__ flag, int* __restrict__ out) {
    int i = blockIdx.x * blockDim.x + threadIdx.x;
    if (i >= n) return;
    if (*flag) out[i] = (int)((const long long*)raw)[i];
    else       out[i] = ((const int*)raw)[i];
}

// ---------------- prep kernels --------------------------------------------------
__global__ void dinv_kernel(const int* __restrict__ deg, float* __restrict__ dinv, int n) {
    int i = blockIdx.x * blockDim.x + threadIdx.x;
    if (i < n) dinv[i] = rsqrtf((float)deg[i] + 1.0f);
}

__global__ void scale0_kernel(const float* __restrict__ x, const float* __restrict__ dinv,
                              __half* __restrict__ xs, int total) {
    int i = blockIdx.x * blockDim.x + threadIdx.x;
    if (i < total) xs[i] = __float2half_rn(x[i] * dinv[i >> 6]);
}

__global__ void round_h_kernel(const float* __restrict__ in, __half* __restrict__ out, int n) {
    int i = blockIdx.x * blockDim.x + threadIdx.x;
    if (i < n) out[i] = __float2half_rn(in[i]);
}

__global__ void stack_h_kernel(const float* __restrict__ B1, const float* __restrict__ B2,
                               __half* __restrict__ out, int K1, int Ktot) {
    int i = blockIdx.x * blockDim.x + threadIdx.x;
    if (i >= Ktot * 256) return;
    int k = i >> 8, c = i & 255;
    float v = (k < K1) ? B1[k * 256 + c] : B2[(k - K1) * 256 + c];
    out[i] = __float2half_rn(v);
}

__global__ void scan_kernel(const int* __restrict__ deg, int* __restrict__ rowptr, int n) {
    __shared__ int sums[1024];
    int t = threadIdx.x;
    int chunk = (n + 1023) / 1024;
    int s = t * chunk;
    int e = min(s + chunk, n);
    int acc = 0;
    for (int i = s; i < e; i++) acc += deg[i];
    sums[t] = acc;
    __syncthreads();
    for (int d = 1; d < 1024; d <<= 1) {
        int v = (t >= d) ? sums[t - d] : 0;
        __syncthreads();
        sums[t] += v;
        __syncthreads();
    }
    int off = (t == 0) ? 0 : sums[t - 1];
    for (int i = s; i < e; i++) { rowptr[i] = off; off += deg[i]; }
    if (t == 1023) rowptr[n] = sums[1023];
}

__global__ void fill_csr_kernel(const int* __restrict__ src, const int* __restrict__ dst, int E,
                                const int* __restrict__ rowptr, int* __restrict__ cur,
                                int* __restrict__ col) {
    int i = blockIdx.x * blockDim.x + threadIdx.x;
    if (i >= E) return;
    int d = dst[i];
    int pos = rowptr[d] + atomicAdd(&cur[d], 1);
    col[pos] = src[i];
}

// ---------------- input-space aggregation (fp16 gather, fp32 accumulate) -------
template <int C>
__global__ void aggregate_kernel(const __half* __restrict__ xs,
                                 const int* __restrict__ rowptr, const int* __restrict__ col,
                                 const float* __restrict__ dinv,
                                 __half* __restrict__ out, int ldo, int n)
{
    int node = (blockIdx.x * blockDim.x + threadIdx.x) >> 5;
    if (node >= n) return;
    int lane = threadIdx.x & 31;
    constexpr int F  = C / 32;   // halfs per lane: 2, 4, 8
    constexpr int HV = F / 2;    // half2 per lane

    float acc[F];

    auto addRow = [&](const __half* p, bool init) {
        half2 h[HV];
        if constexpr (F == 2) {
            *(uint32_t*)h = *(const uint32_t*)p;
        } else if constexpr (F == 4) {
            *(uint2*)h = *(const uint2*)p;
        } else {
            *(uint4*)h = *(const uint4*)p;
        }
        #pragma unroll
        for (int j = 0; j < HV; j++) {
            float2 f = __half22float2(h[j]);
            if (init) { acc[2 * j] = f.x; acc[2 * j + 1] = f.y; }
            else      { acc[2 * j] += f.x; acc[2 * j + 1] += f.y; }
        }
    };

    addRow(xs + (size_t)node * C + lane * F, true);

    int s = rowptr[node], e = rowptr[node + 1];
    int k = s;
    for (; k + 3 < e; k += 4) {
        int u0 = col[k], u1 = col[k + 1], u2 = col[k + 2], u3 = col[k + 3];
        addRow(xs + (size_t)u0 * C + lane * F, false);
        addRow(xs + (size_t)u1 * C + lane * F, false);
        addRow(xs + (size_t)u2 * C + lane * F, false);
        addRow(xs + (size_t)u3 * C + lane * F, false);
    }
    for (; k < e; k++) addRow(xs + (size_t)col[k] * C + lane * F, false);

    float dv = dinv[node];
    half2* orow = (half2*)(out + (size_t)node * ldo + lane * F);
    #pragma unroll
    for (int j = 0; j < HV; j++)
        orow[j] = __floats2half2_rn(dv * acc[2 * j], dv * acc[2 * j + 1]);
}

// ---------------- fp16 pipelined GEMM -------------------------------------------
// C = A[MxK] @ B[KxN] (both __half, row-major, lda=K, ldb=N); K%32==0, N%128==0.
// If Cf != null: write raw fp32 accum to Cf (ldc). Else: v = acc + bias1 + bias2,
// relu, round to half -> Ch[ldc]; optionally C2[ld2] = half(dinv[r] * v).
__global__ __launch_bounds__(256, 2) void gemm_h_kernel(
    const __half* __restrict__ A, const __half* __restrict__ B,
    __half* __restrict__ Ch, float* __restrict__ Cf,
    int M, int N, int K, int ldc,
    const float* __restrict__ bias1, const float* __restrict__ bias2,
    __half* __restrict__ C2, int ld2, const float* __restrict__ dinv)
{
    const int BM = 128, BK = 32;
    const int LDA = 40, LDB = 136;   // halfs
    __shared__ __align__(256) __half As[2][BM * LDA];   // 10240 B / stage
    __shared__ __align__(256) __half Bs[2][BK * LDB];   // 8704 B / stage

    int tid  = threadIdx.x;
    int lane = tid & 31;
    int warp = tid >> 5;
    int warpM = (warp >> 2) * 64;
    int warpN = (warp & 3) * 32;
    int rowBase = blockIdx.y * BM;
    int colBase = blockIdx.x * 128;

    wmma::fragment<wmma::accumulator, 16, 16, 16, float> acc[4][2];
    #pragma unroll
    for (int m = 0; m < 4; m++)
        #pragma unroll
        for (int n = 0; n < 2; n++) wmma::fill_fragment(acc[m][n], 0.0f);

    int ntiles = K / BK;

    uint32_t asBase[2], bsBase[2];
    asBase[0] = (uint32_t)__cvta_generic_to_shared(&As[0][0]);
    asBase[1] = (uint32_t)__cvta_generic_to_shared(&As[1][0]);
    bsBase[0] = (uint32_t)__cvta_generic_to_shared(&Bs[0][0]);
    bsBase[1] = (uint32_t)__cvta_generic_to_shared(&Bs[1][0]);

    auto issue = [&](int t, int s) {
        int k0 = t * BK;
        // A tile: 128 rows x 32 halfs = 512 chunks of 16B (8 halfs)
        #pragma unroll
        for (int h = 0; h < 2; h++) {
            int c = tid + h * 256;
            int row = c >> 2, q = c & 3;
            int r = rowBase + row;
            bool ok = (r < M);
            const __half* src = A + (size_t)(ok ? r : 0) * K + k0 + q * 8;
            cp16(asBase[s] + (uint32_t)(row * LDA + q * 8) * 2u, src, ok);
        }
        // B tile: 32 rows x 128 halfs = 512 chunks
        #pragma unroll
        for (int h = 0; h < 2; h++) {
            int c = tid + h * 256;
            int row = c >> 4, q = c & 15;
            const __half* src = B + (size_t)(k0 + row) * N + colBase + q * 8;
            cp16(bsBase[s] + (uint32_t)(row * LDB + q * 8) * 2u, src, true);
        }
    };

    issue(0, 0);
    cp_commit();

    for (int t = 0; t < ntiles; t++) {
        cp_wait0();
        __syncthreads();
        if (t + 1 < ntiles) { issue(t + 1, (t + 1) & 1); cp_commit(); }

        const __half* as = As[t & 1];
        const __half* bs = Bs[t & 1];
        #pragma unroll
        for (int kk = 0; kk < BK; kk += 16) {
            wmma::fragment<wmma::matrix_a, 16, 16, 16, __half, wmma::row_major> af[4];
            wmma::fragment<wmma::matrix_b, 16, 16, 16, __half, wmma::row_major> bf[2];
            #pragma unroll
            for (int m = 0; m < 4; m++)
                wmma::load_matrix_sync(af[m], as + (warpM + 16 * m) * LDA + kk, LDA);
            #pragma unroll
            for (int n = 0; n < 2; n++)
                wmma::load_matrix_sync(bf[n], bs + kk * LDB + warpN + 16 * n, LDB);
            #pragma unroll
            for (int m = 0; m < 4; m++)
                #pragma unroll
                for (int n = 0; n < 2; n++)
                    wmma::mma_sync(acc[m][n], af[m], bf[n], acc[m][n]);
        }
    }
    __syncthreads();

    // epilogue via smem staging (reuse As as float scratch: 8*320 floats = 10240 B)
    float* es = (float*)&As[0][0] + warp * 320;
    #pragma unroll
    for (int m = 0; m < 4; m++) {
        #pragma unroll
        for (int n = 0; n < 2; n++) {
            wmma::store_matrix_sync(es, acc[m][n], 20, wmma::mem_row_major);
            __syncwarp();
            #pragma unroll
            for (int i = 0; i < 2; i++) {
                int r  = i * 8 + (lane >> 2);
                int c4 = (lane & 3) * 4;
                int gr = rowBase + warpM + 16 * m + r;
                int gc = colBase + warpN + 16 * n + c4;
                if (gr < M) {
                    float4 v = *(float4*)(es + r * 20 + c4);
                    if (Cf) {
                        *(float4*)(Cf + (size_t)gr * ldc + gc) = v;
                    } else {
                        if (bias1) {
                            v.x += bias1[gc]; v.y += bias1[gc + 1];
                            v.z += bias1[gc + 2]; v.w += bias1[gc + 3];
                        }
                        if (bias2) {
                            v.x += bias2[gc]; v.y += bias2[gc + 1];
                            v.z += bias2[gc + 2]; v.w += bias2[gc + 3];
                        }
                        v.x = fmaxf(v.x, 0.f); v.y = fmaxf(v.y, 0.f);
                        v.z = fmaxf(v.z, 0.f); v.w = fmaxf(v.w, 0.f);
                        half2 h0 = __floats2half2_rn(v.x, v.y);
                        half2 h1 = __floats2half2_rn(v.z, v.w);
                        half2* cp = (half2*)(Ch + (size_t)gr * ldc + gc);
                        cp[0] = h0; cp[1] = h1;
                        if (C2) {
                            float dv = dinv[gr];
                            float2 f0 = __half22float2(h0);
                            float2 f1 = __half22float2(h1);
                            half2* c2 = (half2*)(C2 + (size_t)gr * ld2 + gc);
                            c2[0] = __floats2half2_rn(dv * f0.x, dv * f0.y);
                            c2[1] = __floats2half2_rn(dv * f1.x, dv * f1.y);
                        }
                    }
                }
            }
            __syncwarp();
        }
    }
}

// ---------------- legacy tf32 GEMM (K tails / atomics) for fp/fg ---------------
__global__ __launch_bounds__(256, 2) void gemm_tc_kernel(
    const float* __restrict__ A, const float* __restrict__ B, float* __restrict__ C,
    int M, int N, int K, int kChunk, int atomicOut)
{
    const int BM = 128, BN = 128, BK = 16;
    const int LDA = 20, LDB = 132;
    __shared__ __align__(16) float As[BM * LDA];
    __shared__ __align__(16) float Bs[BK * LDB];

    int tid  = threadIdx.x;
    int lane = tid & 31;
    int warp = tid >> 5;
    int warpM = (warp >> 2) * 64;
    int warpN = (warp & 3) * 32;

    int rowBase = blockIdx.y * BM;
    int colBase = blockIdx.x * BN;
    int kStart  = blockIdx.z * kChunk;
    int kEnd    = min(K, kStart + kChunk);

    wmma::fragment<wmma::accumulator, 16, 16, 8, float> acc[4][2];
    #pragma unroll
    for (int m = 0; m < 4; m++)
        #pragma unroll
        for (int n = 0; n < 2; n++) wmma::fill_fragment(acc[m][n], 0.0f);

    bool kAligned = ((K & 3) == 0);
    int aRow = tid >> 1, aCol = (tid & 1) * 8;
    int bRow = tid >> 4, bCol = (tid & 15) * 8;

    for (int k0 = kStart; k0 < kEnd; k0 += BK) {
        {
            int r = rowBase + aRow;
            #pragma unroll
            for (int j = 0; j < 2; j++) {
                int cb = k0 + aCol + j * 4;
                float4 v = make_float4(0.f, 0.f, 0.f, 0.f);
                if (r < M) {
                    if (kAligned && (cb + 3 < kEnd)) {
                        v = *(const float4*)(A + (size_t)r * K + cb);
                    } else {
                        if (cb + 0 < kEnd) v.x = A[(size_t)r * K + cb + 0];
                        if (cb + 1 < kEnd) v.y = A[(size_t)r * K + cb + 1];
                        if (cb + 2 < kEnd) v.z = A[(size_t)r * K + cb + 2];
                        if (cb + 3 < kEnd) v.w = A[(size_t)r * K + cb + 3];
                    }
                }
                float* dstp = As + aRow * LDA + aCol + j * 4;
                dstp[0] = tf32r(v.x); dstp[1] = tf32r(v.y);
                dstp[2] = tf32r(v.z); dstp[3] = tf32r(v.w);
            }
        }
        {
            int kr = k0 + bRow;
            #pragma unroll
            for (int j = 0; j < 2; j++) {
                float4 v = make_float4(0.f, 0.f, 0.f, 0.f);
                if (kr < kEnd) v = *(const float4*)(B + (size_t)kr * N + colBase + bCol + j * 4);
                float* dstp = Bs + bRow * LDB + bCol + j * 4;
                dstp[0] = tf32r(v.x); dstp[1] = tf32r(v.y);
                dstp[2] = tf32r(v.z); dstp[3] = tf32r(v.w);
            }
        }
        __syncthreads();

        #pragma unroll
        for (int kk = 0; kk < BK; kk += 8) {
            wmma::fragment<wmma::matrix_a, 16, 16, 8, wmma::precision::tf32, wmma::row_major> af[4];
            wmma::fragment<wmma::matrix_b, 16, 16, 8, wmma::precision::tf32, wmma::row_major> bf[2];
            #pragma unroll
            for (int m = 0; m < 4; m++)
                wmma::load_matrix_sync(af[m], As + (warpM + 16 * m) * LDA + kk, LDA);
            #pragma unroll
            for (int n = 0; n < 2; n++)
                wmma::load_matrix_sync(bf[n], Bs + kk * LDB + warpN + 16 * n, LDB);
            #pragma unroll
            for (int m = 0; m < 4; m++)
                #pragma unroll
                for (int n = 0; n < 2; n++)
                    wmma::mma_sync(acc[m][n], af[m], bf[n], acc[m][n]);
        }
        __syncthreads();
    }

    float* es = As + warp * 320;
    #pragma unroll
    for (int m = 0; m < 4; m++) {
        #pragma unroll
        for (int n = 0; n < 2; n++) {
            wmma::store_matrix_sync(es, acc[m][n], 20, wmma::mem_row_major);
            __syncwarp();
            #pragma unroll
            for (int i = 0; i < 2; i++) {
                int r  = i * 8 + (lane >> 2);
                int c4 = (lane & 3) * 4;
                int gr = rowBase + warpM + 16 * m + r;
                int gc = colBase + warpN + 16 * n + c4;
                if (gr < M) {
                    float4 v = *(float4*)(es + r * 20 + c4);
                    float* cp = C + (size_t)gr * N + gc;
                    if (atomicOut) {
                        atomicAdd(cp + 0, v.x); atomicAdd(cp + 1, v.y);
                        atomicAdd(cp + 2, v.z); atomicAdd(cp + 3, v.w);
                    } else {
                        *(float4*)cp = v;
                    }
                }
            }
            __syncwarp();
        }
    }
}

// ---------------- softmax * x3, per-graph pooled mean ---------------------------
__device__ __forceinline__ int lowerb(const int* a, int n, int key) {
    int lo = 0, hi = n;
    while (lo < hi) { int mid = (lo + hi) >> 1; if (a[mid] < key) lo = mid + 1; else hi = mid; }
    return lo;
}

__global__ void softmax_pool_kernel(const float* __restrict__ logits, const __half* __restrict__ x3,
                                    const int* __restrict__ batch,
                                    float* __restrict__ pooled, int n)
{
    __shared__ float sred[8 * 256];
    int g = blockIdx.x;
    int lane = threadIdx.x & 31;
    int w = threadIdx.x >> 5;

    int start = lowerb(batch, n, g);
    int end   = lowerb(batch, n, g + 1);

    float acc[8];
    #pragma unroll
    for (int j = 0; j < 8; j++) acc[j] = 0.f;

    for (int node = start + w; node < end; node += 8) {
        const float4* lr = (const float4*)(logits + (size_t)node * 256 + lane * 8);
        float4 a0 = lr[0], a1 = lr[1];
        float a[8] = {a0.x, a0.y, a0.z, a0.w, a1.x, a1.y, a1.z, a1.w};
        float m = a[0];
        #pragma unroll
        for (int j = 1; j < 8; j++) m = fmaxf(m, a[j]);
        #pragma unroll
        for (int off = 16; off > 0; off >>= 1) m = fmaxf(m, __shfl_xor_sync(0xFFFFFFFFu, m, off));
        float s = 0.f;
        #pragma unroll
        for (int j = 0; j < 8; j++) { a[j] = __expf(a[j] - m); s += a[j]; }
        #pragma unroll
        for (int off = 16; off > 0; off >>= 1) s += __shfl_xor_sync(0xFFFFFFFFu, s, off);
        float inv = 1.f / s;

        half2 hx[4];
        *(uint4*)hx = *(const uint4*)(x3 + (size_t)node * 256 + lane * 8);
        #pragma unroll
        for (int j = 0; j < 4; j++) {
            float2 f = __half22float2(hx[j]);
            acc[2 * j]     += a[2 * j]     * inv * f.x;
            acc[2 * j + 1] += a[2 * j + 1] * inv * f.y;
        }
    }

    #pragma unroll
    for (int j = 0; j < 8; j++) sred[w * 256 + lane * 8 + j] = acc[j];
    __syncthreads();

    int t = threadIdx.x;
    float v = 0.f;
    #pragma unroll
    for (int ww = 0; ww < 8; ww++) v += sred[ww * 256 + t];
    float invc = 1.f / fmaxf((float)(end - start), 1.f);
    pooled[(size_t)g * 256 + t] = v * invc;
}

// ---------------- final ---------------------------------------------------------
__global__ void final_kernel(const float* __restrict__ pooled,
                             const float* __restrict__ fpa, const float* __restrict__ fga,
                             const float* __restrict__ bfp, const float* __restrict__ bfg,
                             const float* __restrict__ Wfc, const float* __restrict__ bfc,
                             float* __restrict__ out, int B)
{
    int warp = (blockIdx.x * blockDim.x + threadIdx.x) >> 5;
    if (warp >= B) return;
    int lane = threadIdx.x & 31;
    float s = 0.f;
    #pragma unroll
    for (int j = 0; j < 8; j++) {
        int idx = lane * 8 + j;
        size_t o = (size_t)warp * 256 + idx;
        float v = pooled[o]
                + fmaxf(fpa[o] + bfp[idx], 0.f)
                + fmaxf(fga[o] + bfg[idx], 0.f);
        s += v * Wfc[idx];
    }
    #pragma unroll
    for (int off = 16; off > 0; off >>= 1) s += __shfl_xor_sync(0xFFFFFFFFu, s, off);
    if (lane == 0) out[warp] = s + bfc[0];
}

// ---------------- host launcher -------------------------------------------------
extern "C" void kernel_launch(void* const* d_in, const int* in_sizes, int n_in,
                              void* d_out, int out_size)
{
    const float* x    = (const float*)d_in[0];
    const void*  eraw = d_in[1];
    const void*  braw = d_in[2];
    const float* fpf  = (const float*)d_in[3];
    const float* fgf  = (const float*)d_in[4];
    const float* W1   = (const float*)d_in[5];  const float* b1  = (const float*)d_in[6];
    const float* W2   = (const float*)d_in[7];  const float* b2  = (const float*)d_in[8];
    const float* W3   = (const float*)d_in[9];  const float* b3  = (const float*)d_in[10];
    const float* Wr1  = (const float*)d_in[11]; const float* br1 = (const float*)d_in[12];
    const float* Wr2  = (const float*)d_in[13]; const float* br2 = (const float*)d_in[14];
    const float* Wfp  = (const float*)d_in[15]; const float* bfp = (const float*)d_in[16];
    const float* Wfg  = (const float*)d_in[17]; const float* bfg = (const float*)d_in[18];
    const float* attn_W = (const float*)d_in[19];
    const float* Wfc  = (const float*)d_in[20]; const float* bfc = (const float*)d_in[21];
    float* out = (float*)d_out;

    int N = in_sizes[0] / 64;
    int E = in_sizes[1] / 2;
    int B = in_sizes[3] / 2048;

    __half *xs0, *A1, *A2, *xs1, *A3, *xs2, *x3;
    __half *w1r, *w2s, *w3s, *wattn;
    float *work, *dinv, *pooled, *fp, *fg;
    int *eidx, *batch, *deg, *rowptr, *cur, *col, *flag;
    cudaGetSymbolAddress((void**)&eidx,   g_eidx);
    cudaGetSymbolAddress((void**)&batch,  g_batch);
    cudaGetSymbolAddress((void**)&deg,    g_deg);
    cudaGetSymbolAddress((void**)&rowptr, g_rowptr);
    cudaGetSymbolAddress((void**)&cur,    g_cur);
    cudaGetSymbolAddress((void**)&col,    g_col);
    cudaGetSymbolAddress((void**)&flag,   g_flag);
    cudaGetSymbolAddress((void**)&dinv,   g_dinv);
    cudaGetSymbolAddress((void**)&xs0,    g_xs0);
    cudaGetSymbolAddress((void**)&A1,     g_A1);
    cudaGetSymbolAddress((void**)&A2,     g_A2);
    cudaGetSymbolAddress((void**)&xs1,    g_xs1);
    cudaGetSymbolAddress((void**)&A3,     g_A3);
    cudaGetSymbolAddress((void**)&xs2,    g_xs2);
    cudaGetSymbolAddress((void**)&x3,     g_x3);
    cudaGetSymbolAddress((void**)&work,   g_work);
    cudaGetSymbolAddress((void**)&w1r,    g_w1r);
    cudaGetSymbolAddress((void**)&w2s,    g_w2s);
    cudaGetSymbolAddress((void**)&w3s,    g_w3s);
    cudaGetSymbolAddress((void**)&wattn,  g_wattn);
    cudaGetSymbolAddress((void**)&pooled, g_pool);
    cudaGetSymbolAddress((void**)&fp,     g_fp);
    cudaGetSymbolAddress((void**)&fg,     g_fg);

    cudaMemsetAsync(deg, 0, N * sizeof(int));
    cudaMemsetAsync(cur, 0, N * sizeof(int));
    cudaMemsetAsync(fp,  0, (size_t)B * 256 * sizeof(float));
    cudaMemsetAsync(fg,  0, (size_t)B * 256 * sizeof(float));

    // dtype detect + index conversion + degree
    detect_kernel<<<1, 32>>>((const unsigned int*)eraw, flag);
    cvt_edges_kernel<<<(E + 255) / 256, 256>>>(eraw, E, flag, eidx, deg);
    cvt_idx_kernel<<<(N + 255) / 256, 256>>>(braw, N, flag, batch);
    const int* srcA = eidx;
    const int* dstA = eidx + E;

    dinv_kernel<<<(N + 255) / 256, 256>>>(deg, dinv, N);
    scale0_kernel<<<(N * 64 + 255) / 256, 256>>>(x, dinv, xs0, N * 64);

    // weight prep (fp16, stacked)
    round_h_kernel<<<(64 * 128 + 255) / 256, 256>>>(W1, w1r, 64 * 128);
    stack_h_kernel<<<(256 * 256 + 255) / 256, 256>>>(W2, Wr1, w2s, 128, 256);
    stack_h_kernel<<<(512 * 256 + 255) / 256, 256>>>(W3, Wr2, w3s, 256, 512);
    round_h_kernel<<<(256 * 256 + 255) / 256, 256>>>(attn_W, wattn, 256 * 256);

    // CSR
    scan_kernel<<<1, 1024>>>(deg, rowptr, N);
    fill_csr_kernel<<<(E + 255) / 256, 256>>>(srcA, dstA, E, rowptr, cur, col);

    int aggBlocks = (N * 32 + 255) / 256;
    int gy = (N + 127) / 128;

    // Layer 1: z1 = agg(xs0); x1 = relu(z1@W1 + b1) -> A2[:,128:256], xs1 = dinv*x1
    aggregate_kernel<64><<<aggBlocks, 256>>>(xs0, rowptr, col, dinv, A1, 64, N);
    gemm_h_kernel<<<dim3(1, gy), 256>>>(A1, w1r, A2 + 128, nullptr, N, 128, 64, 256,
                                        b1, nullptr, xs1, 128, dinv);

    // Layer 2: z2 = agg(xs1) -> A2[:,0:128]; x2 = relu([z2|x1]@[W2;Wr1] + b2 + br1)
    aggregate_kernel<128><<<aggBlocks, 256>>>(xs1, rowptr, col, dinv, A2, 256, N);
    gemm_h_kernel<<<dim3(2, gy), 256>>>(A2, w2s, A3 + 256, nullptr, N, 256, 256, 512,
                                        b2, br1, xs2, 256, dinv);

    // Layer 3: z3 = agg(xs2) -> A3[:,0:256]; x3 = relu([z3|x2]@[W3;Wr2] + b3 + br2)
    aggregate_kernel<256><<<aggBlocks, 256>>>(xs2, rowptr, col, dinv, A3, 512, N);
    gemm_h_kernel<<<dim3(2, gy), 256>>>(A3, w3s, x3, nullptr, N, 256, 512, 256,
                                        b3, br2, nullptr, 0, nullptr);

    // Attention logits (fp32 output — half rounding of O(250) logits would break softmax)
    gemm_h_kernel<<<dim3(2, gy), 256>>>(x3, wattn, nullptr, work, N, 256, 256, 256,
                                        nullptr, nullptr, nullptr, 0, nullptr);

    // fp / fg (legacy tf32 kernel, split-K atomics for fp)
    gemm_tc_kernel<<<dim3(2, (B + 127) / 128, 8), 256>>>(fpf, Wfp, fp, B, 256, 2048, 256, 1);
    gemm_tc_kernel<<<dim3(2, (B + 127) / 128, 1), 256>>>(fgf, Wfg, fg, B, 256, 167, 167, 1);

    // softmax * x3 -> per-graph pooled mean
    softmax_pool_kernel<<<B, 256>>>(work, x3, batch, pooled, N);

    // final projection
    final_kernel<<<(B * 32 + 255) / 256, 256>>>(pooled, fp, fg, bfp, bfg, Wfc, bfc, out, B);
}

// round 7
// speedup vs baseline: 3.9255x; 1.1775x over previous
#include <cuda_runtime.h>
#include <cuda_fp16.h>
#include <cstdint>
#include <mma.h>
#include <math.h>

using namespace nvcuda;

#define NODES_MAX 50000
#define EDGES_MAX 800000
#define GRAPHS_MAX 1024

// ---------------- scratch (device globals) ------------------------------------
__device__ int    g_eidx[2 * EDGES_MAX];
__device__ int    g_batch[NODES_MAX];
__device__ int    g_deg[NODES_MAX];
__device__ int    g_rowptr[NODES_MAX + 1];
__device__ int    g_cur[NODES_MAX];
__device__ int    g_col[EDGES_MAX];
__device__ int    g_flag[1];
__device__ float  g_dinv[NODES_MAX];
__device__ __half g_xs0[(size_t)NODES_MAX * 64];
__device__ __half g_A1 [(size_t)NODES_MAX * 64];
__device__ __half g_A2 [(size_t)NODES_MAX * 256];   // [z2 | x1]
__device__ __half g_xs1[(size_t)NODES_MAX * 128];
__device__ __half g_A3 [(size_t)NODES_MAX * 512];   // [z3 | x2]
__device__ __half g_xs2[(size_t)NODES_MAX * 256];
__device__ __half g_x3 [(size_t)NODES_MAX * 256];
__device__ float  g_work[(size_t)NODES_MAX * 256];  // attn logits (fp32!)
__device__ __half g_w1r[64 * 128];
__device__ __half g_w2s[256 * 256];                 // [W2 ; Wr1]
__device__ __half g_w3s[512 * 256];                 // [W3 ; Wr2]
__device__ __half g_wattn[256 * 256];
__device__ __half g_fph [1024 * 2048];
__device__ __half g_wfph[2048 * 256];
__device__ __half g_fgp [1024 * 192];
__device__ __half g_wfgp[192 * 256];
__device__ float  g_pool[GRAPHS_MAX * 256];
__device__ float  g_fp[GRAPHS_MAX * 256];
__device__ float  g_fg[GRAPHS_MAX * 256];

__device__ __forceinline__ void cp16(uint32_t dst, const void* src, bool pred) {
    int bytes = pred ? 16 : 0;
    asm volatile("cp.async.cg.shared.global [%0], [%1], 16, %2;\n"
                 :: "r"(dst), "l"(src), "r"(bytes));
}
__device__ __forceinline__ void cp_commit() { asm volatile("cp.async.commit_group;\n"); }
__device__ __forceinline__ void cp_wait0()  { asm volatile("cp.async.wait_group 0;\n"); }
__device__ __forceinline__ void cp_wait1g() { asm volatile("cp.async.wait_group 1;\n"); }

// ---------------- dtype detect + index convert --------------------------------
__global__ void detect_kernel(const unsigned int* __restrict__ w, int* __restrict__ flag) {
    int t = threadIdx.x;
    unsigned int v = w[2 * t + 1] | w[2 * (t + 32) + 1] | w[2 * (t + 64) + 1] | w[2 * (t + 96) + 1];
    unsigned int nz = __ballot_sync(0xFFFFFFFFu, v != 0u);
    if (t == 0) *flag = (nz == 0u) ? 1 : 0;
}

__global__ void cvt_edges_kernel(const void* __restrict__ raw, int E,
                                 const int* __restrict__ flag, int* __restrict__ eidx,
                                 int* __restrict__ deg) {
    int i = blockIdx.x * blockDim.x + threadIdx.x;
    if (i >= E) return;
    int s, d;
    if (*flag) {
        s = (int)((const long long*)raw)[i];
        d = (int)((const long long*)raw)[E + i];
    } else {
        s = ((const int*)raw)[i];
        d = ((const int*)raw)[E + i];
    }
    eidx[i] = s;
    eidx[E + i] = d;
    atomicAdd(&deg[d], 1);
}

__global__ void cvt_idx_kernel(const void* __restrict__ raw, int n,
                               const int* __restrict__ flag, int* __restrict__ out) {
    int i = blockIdx.x * blockDim.x + threadIdx.x;
    if (i >= n) return;
    if (*flag) out[i] = (int)((const long long*)raw)[i];
    else       out[i] = ((const int*)raw)[i];
}

// ---------------- prep kernels --------------------------------------------------
__global__ void dinv_kernel(const int* __restrict__ deg, float* __restrict__ dinv, int n) {
    int i = blockIdx.x * blockDim.x + threadIdx.x;
    if (i < n) dinv[i] = rsqrtf((float)deg[i] + 1.0f);
}

__global__ void scale0_kernel(const float* __restrict__ x, const float* __restrict__ dinv,
                              __half* __restrict__ xs, int total) {
    int i = blockIdx.x * blockDim.x + threadIdx.x;
    if (i < total) xs[i] = __float2half_rn(x[i] * dinv[i >> 6]);
}

// single mega prep kernel: all weight conversions / stacks / pads
__global__ void prep_kernel(
    const float* __restrict__ W1, const float* __restrict__ W2, const float* __restrict__ Wr1,
    const float* __restrict__ W3, const float* __restrict__ Wr2, const float* __restrict__ attn_W,
    const float* __restrict__ fpf, const float* __restrict__ Wfp,
    const float* __restrict__ fgf, const float* __restrict__ Wfg,
    __half* __restrict__ w1r, __half* __restrict__ w2s, __half* __restrict__ w3s,
    __half* __restrict__ wattn, __half* __restrict__ fph, __half* __restrict__ wfph,
    __half* __restrict__ fgp, __half* __restrict__ wfgp)
{
    int j = blockIdx.x * blockDim.x + threadIdx.x;
    // S0: w1r [8192]
    if (j < 8192) { w1r[j] = __float2half_rn(W1[j]); return; }
    j -= 8192;
    // S1: w2s [65536] = stack(W2[128x256], Wr1[128x256])
    if (j < 65536) {
        int k = j >> 8, c = j & 255;
        float v = (k < 128) ? W2[k * 256 + c] : Wr1[(k - 128) * 256 + c];
        w2s[j] = __float2half_rn(v); return;
    }
    j -= 65536;
    // S2: w3s [131072] = stack(W3[256x256], Wr2[256x256])
    if (j < 131072) {
        int k = j >> 8, c = j & 255;
        float v = (k < 256) ? W3[k * 256 + c] : Wr2[(k - 256) * 256 + c];
        w3s[j] = __float2half_rn(v); return;
    }
    j -= 131072;
    // S3: wattn [65536]
    if (j < 65536) { wattn[j] = __float2half_rn(attn_W[j]); return; }
    j -= 65536;
    // S4: fph [2097152]
    if (j < 2097152) { fph[j] = __float2half_rn(fpf[j]); return; }
    j -= 2097152;
    // S5: wfph [524288]
    if (j < 524288) { wfph[j] = __float2half_rn(Wfp[j]); return; }
    j -= 524288;
    // S6: fgp [1024 x 192], pad K 167 -> 192
    if (j < 196608) {
        int r = j / 192, c = j % 192;
        fgp[j] = __float2half_rn(c < 167 ? fgf[r * 167 + c] : 0.f); return;
    }
    j -= 196608;
    // S7: wfgp [192 x 256], pad rows 167 -> 192
    if (j < 49152) {
        int k = j >> 8, c = j & 255;
        wfgp[j] = __float2half_rn(k < 167 ? Wfg[k * 256 + c] : 0.f); return;
    }
}
#define PREP_TOTAL (8192 + 65536 + 131072 + 65536 + 2097152 + 524288 + 196608 + 49152)

__global__ void scan_kernel(const int* __restrict__ deg, int* __restrict__ rowptr, int n) {
    __shared__ int sums[1024];
    int t = threadIdx.x;
    int chunk = (n + 1023) / 1024;
    int s = t * chunk;
    int e = min(s + chunk, n);
    int acc = 0;
    for (int i = s; i < e; i++) acc += deg[i];
    sums[t] = acc;
    __syncthreads();
    for (int d = 1; d < 1024; d <<= 1) {
        int v = (t >= d) ? sums[t - d] : 0;
        __syncthreads();
        sums[t] += v;
        __syncthreads();
    }
    int off = (t == 0) ? 0 : sums[t - 1];
    for (int i = s; i < e; i++) { rowptr[i] = off; off += deg[i]; }
    if (t == 1023) rowptr[n] = sums[1023];
}

__global__ void fill_csr_kernel(const int* __restrict__ src, const int* __restrict__ dst, int E,
                                const int* __restrict__ rowptr, int* __restrict__ cur,
                                int* __restrict__ col) {
    int i = blockIdx.x * blockDim.x + threadIdx.x;
    if (i >= E) return;
    int d = dst[i];
    int pos = rowptr[d] + atomicAdd(&cur[d], 1);
    col[pos] = src[i];
}

// ---------------- input-space aggregation (fp16 gather, fp32 accumulate) -------
template <int C>
__global__ void aggregate_kernel(const __half* __restrict__ xs,
                                 const int* __restrict__ rowptr, const int* __restrict__ col,
                                 const float* __restrict__ dinv,
                                 __half* __restrict__ out, int ldo, int n)
{
    int node = (blockIdx.x * blockDim.x + threadIdx.x) >> 5;
    if (node >= n) return;
    int lane = threadIdx.x & 31;
    constexpr int F  = C / 32;
    constexpr int HV = F / 2;

    float acc[F];

    auto addRow = [&](const __half* p, bool init) {
        half2 h[HV];
        if constexpr (F == 2) {
            *(uint32_t*)h = *(const uint32_t*)p;
        } else if constexpr (F == 4) {
            *(uint2*)h = *(const uint2*)p;
        } else {
            *(uint4*)h = *(const uint4*)p;
        }
        #pragma unroll
        for (int j = 0; j < HV; j++) {
            float2 f = __half22float2(h[j]);
            if (init) { acc[2 * j] = f.x; acc[2 * j + 1] = f.y; }
            else      { acc[2 * j] += f.x; acc[2 * j + 1] += f.y; }
        }
    };

    addRow(xs + (size_t)node * C + lane * F, true);

    int s = rowptr[node], e = rowptr[node + 1];
    int k = s;
    for (; k + 3 < e; k += 4) {
        int u0 = col[k], u1 = col[k + 1], u2 = col[k + 2], u3 = col[k + 3];
        addRow(xs + (size_t)u0 * C + lane * F, false);
        addRow(xs + (size_t)u1 * C + lane * F, false);
        addRow(xs + (size_t)u2 * C + lane * F, false);
        addRow(xs + (size_t)u3 * C + lane * F, false);
    }
    for (; k < e; k++) addRow(xs + (size_t)col[k] * C + lane * F, false);

    float dv = dinv[node];
    half2* orow = (half2*)(out + (size_t)node * ldo + lane * F);
    #pragma unroll
    for (int j = 0; j < HV; j++)
        orow[j] = __floats2half2_rn(dv * acc[2 * j], dv * acc[2 * j + 1]);
}

// ---------------- fp16 GEMM, 3-stage cp.async pipeline --------------------------
// C = A[MxK] @ B[KxN] (half, row-major, lda=K, ldb=N); (kEnd-kStart)%32==0, N%128==0.
// kChunk: K-range per z-block. Cf path: raw fp32 accum (atomicOut? add : store).
// Ch path: v = acc + bias1 + bias2; relu; half -> Ch; optionally C2 = half(dinv*v).
#define GEMM_AS 5120          // halfs per A stage (128*40)
#define GEMM_BS 4352          // halfs per B stage (32*136)
#define GEMM_STAGE (GEMM_AS + GEMM_BS)
#define GEMM_SMEM (3 * GEMM_STAGE * 2)   // bytes = 56832

__global__ __launch_bounds__(256) void gemm_h_kernel(
    const __half* __restrict__ A, const __half* __restrict__ B,
    __half* __restrict__ Ch, float* __restrict__ Cf,
    int M, int N, int K, int ldc, int kChunk, int atomicOut,
    const float* __restrict__ bias1, const float* __restrict__ bias2,
    __half* __restrict__ C2, int ld2, const float* __restrict__ dinv)
{
    extern __shared__ __half sm[];
    const int BM = 128, BK = 32;
    const int LDA = 40, LDB = 136;

    int tid  = threadIdx.x;
    int lane = tid & 31;
    int warp = tid >> 5;
    int warpM = (warp >> 2) * 64;
    int warpN = (warp & 3) * 32;
    int rowBase = blockIdx.y * BM;
    int colBase = blockIdx.x * 128;

    int kStart = blockIdx.z * kChunk;
    int kEnd   = min(K, kStart + kChunk);
    int ntiles = (kEnd - kStart) / BK;

    wmma::fragment<wmma::accumulator, 16, 16, 16, float> acc[4][2];
    #pragma unroll
    for (int m = 0; m < 4; m++)
        #pragma unroll
        for (int n = 0; n < 2; n++) wmma::fill_fragment(acc[m][n], 0.0f);

    uint32_t smBase = (uint32_t)__cvta_generic_to_shared(sm);

    auto issue = [&](int t, int s) {
        int k0 = kStart + t * BK;
        uint32_t asB = smBase + (uint32_t)(s * GEMM_STAGE) * 2u;
        uint32_t bsB = asB + (uint32_t)GEMM_AS * 2u;
        #pragma unroll
        for (int h = 0; h < 2; h++) {
            int c = tid + h * 256;
            int row = c >> 2, q = c & 3;
            int r = rowBase + row;
            bool ok = (r < M);
            const __half* src = A + (size_t)(ok ? r : 0) * K + k0 + q * 8;
            cp16(asB + (uint32_t)(row * LDA + q * 8) * 2u, src, ok);
        }
        #pragma unroll
        for (int h = 0; h < 2; h++) {
            int c = tid + h * 256;
            int row = c >> 4, q = c & 15;
            const __half* src = B + (size_t)(k0 + row) * N + colBase + q * 8;
            cp16(bsB + (uint32_t)(row * LDB + q * 8) * 2u, src, true);
        }
    };

    issue(0, 0);
    cp_commit();
    if (ntiles > 1) { issue(1, 1); cp_commit(); }

    int s = 0;
    for (int t = 0; t < ntiles; t++) {
        if (t + 1 < ntiles) cp_wait1g(); else cp_wait0();
        __syncthreads();
        if (t + 2 < ntiles) {
            int s2 = s + 2; if (s2 >= 3) s2 -= 3;
            issue(t + 2, s2);
            cp_commit();
        }

        const __half* as = sm + s * GEMM_STAGE;
        const __half* bs = as + GEMM_AS;
        #pragma unroll
        for (int kk = 0; kk < BK; kk += 16) {
            wmma::fragment<wmma::matrix_a, 16, 16, 16, __half, wmma::row_major> af[4];
            wmma::fragment<wmma::matrix_b, 16, 16, 16, __half, wmma::row_major> bf[2];
            #pragma unroll
            for (int m = 0; m < 4; m++)
                wmma::load_matrix_sync(af[m], as + (warpM + 16 * m) * LDA + kk, LDA);
            #pragma unroll
            for (int n = 0; n < 2; n++)
                wmma::load_matrix_sync(bf[n], bs + kk * LDB + warpN + 16 * n, LDB);
            #pragma unroll
            for (int m = 0; m < 4; m++)
                #pragma unroll
                for (int n = 0; n < 2; n++)
                    wmma::mma_sync(acc[m][n], af[m], bf[n], acc[m][n]);
        }
        if (++s >= 3) s = 0;
    }
    __syncthreads();

    // epilogue via smem staging (reuse stage 0 as float scratch: 8*320*4 = 10240 B)
    float* es = (float*)sm + warp * 320;
    #pragma unroll
    for (int m = 0; m < 4; m++) {
        #pragma unroll
        for (int n = 0; n < 2; n++) {
            wmma::store_matrix_sync(es, acc[m][n], 20, wmma::mem_row_major);
            __syncwarp();
            #pragma unroll
            for (int i = 0; i < 2; i++) {
                int r  = i * 8 + (lane >> 2);
                int c4 = (lane & 3) * 4;
                int gr = rowBase + warpM + 16 * m + r;
                int gc = colBase + warpN + 16 * n + c4;
                if (gr < M) {
                    float4 v = *(float4*)(es + r * 20 + c4);
                    if (Cf) {
                        float* cp = Cf + (size_t)gr * ldc + gc;
                        if (atomicOut) {
                            atomicAdd(cp + 0, v.x); atomicAdd(cp + 1, v.y);
                            atomicAdd(cp + 2, v.z); atomicAdd(cp + 3, v.w);
                        } else {
                            *(float4*)cp = v;
                        }
                    } else {
                        if (bias1) {
                            v.x += bias1[gc]; v.y += bias1[gc + 1];
                            v.z += bias1[gc + 2]; v.w += bias1[gc + 3];
                        }
                        if (bias2) {
                            v.x += bias2[gc]; v.y += bias2[gc + 1];
                            v.z += bias2[gc + 2]; v.w += bias2[gc + 3];
                        }
                        v.x = fmaxf(v.x, 0.f); v.y = fmaxf(v.y, 0.f);
                        v.z = fmaxf(v.z, 0.f); v.w = fmaxf(v.w, 0.f);
                        half2 h0 = __floats2half2_rn(v.x, v.y);
                        half2 h1 = __floats2half2_rn(v.z, v.w);
                        half2* cp = (half2*)(Ch + (size_t)gr * ldc + gc);
                        cp[0] = h0; cp[1] = h1;
                        if (C2) {
                            float dv = dinv[gr];
                            float2 f0 = __half22float2(h0);
                            float2 f1 = __half22float2(h1);
                            half2* c2 = (half2*)(C2 + (size_t)gr * ld2 + gc);
                            c2[0] = __floats2half2_rn(dv * f0.x, dv * f0.y);
                            c2[1] = __floats2half2_rn(dv * f1.x, dv * f1.y);
                        }
                    }
                }
            }
            __syncwarp();
        }
    }
}

// ---------------- softmax * x3, per-graph pooled mean ---------------------------
__device__ __forceinline__ int lowerb(const int* a, int n, int key) {
    int lo = 0, hi = n;
    while (lo < hi) { int mid = (lo + hi) >> 1; if (a[mid] < key) lo = mid + 1; else hi = mid; }
    return lo;
}

__global__ void softmax_pool_kernel(const float* __restrict__ logits, const __half* __restrict__ x3,
                                    const int* __restrict__ batch,
                                    float* __restrict__ pooled, int n)
{
    __shared__ float sred[8 * 256];
    int g = blockIdx.x;
    int lane = threadIdx.x & 31;
    int w = threadIdx.x >> 5;

    int start = lowerb(batch, n, g);
    int end   = lowerb(batch, n, g + 1);

    float acc[8];
    #pragma unroll
    for (int j = 0; j < 8; j++) acc[j] = 0.f;

    for (int node = start + w; node < end; node += 8) {
        const float4* lr = (const float4*)(logits + (size_t)node * 256 + lane * 8);
        float4 a0 = lr[0], a1 = lr[1];
        float a[8] = {a0.x, a0.y, a0.z, a0.w, a1.x, a1.y, a1.z, a1.w};
        float m = a[0];
        #pragma unroll
        for (int j = 1; j < 8; j++) m = fmaxf(m, a[j]);
        #pragma unroll
        for (int off = 16; off > 0; off >>= 1) m = fmaxf(m, __shfl_xor_sync(0xFFFFFFFFu, m, off));
        float s = 0.f;
        #pragma unroll
        for (int j = 0; j < 8; j++) { a[j] = __expf(a[j] - m); s += a[j]; }
        #pragma unroll
        for (int off = 16; off > 0; off >>= 1) s += __shfl_xor_sync(0xFFFFFFFFu, s, off);
        float inv = 1.f / s;

        half2 hx[4];
        *(uint4*)hx = *(const uint4*)(x3 + (size_t)node * 256 + lane * 8);
        #pragma unroll
        for (int j = 0; j < 4; j++) {
            float2 f = __half22float2(hx[j]);
            acc[2 * j]     += a[2 * j]     * inv * f.x;
            acc[2 * j + 1] += a[2 * j + 1] * inv * f.y;
        }
    }

    #pragma unroll
    for (int j = 0; j < 8; j++) sred[w * 256 + lane * 8 + j] = acc[j];
    __syncthreads();

    int t = threadIdx.x;
    float v = 0.f;
    #pragma unroll
    for (int ww = 0; ww < 8; ww++) v += sred[ww * 256 + t];
    float invc = 1.f / fmaxf((float)(end - start), 1.f);
    pooled[(size_t)g * 256 + t] = v * invc;
}

// ---------------- final ---------------------------------------------------------
__global__ void final_kernel(const float* __restrict__ pooled,
                             const float* __restrict__ fpa, const float* __restrict__ fga,
                             const float* __restrict__ bfp, const float* __restrict__ bfg,
                             const float* __restrict__ Wfc, const float* __restrict__ bfc,
                             float* __restrict__ out, int B)
{
    int warp = (blockIdx.x * blockDim.x + threadIdx.x) >> 5;
    if (warp >= B) return;
    int lane = threadIdx.x & 31;
    float s = 0.f;
    #pragma unroll
    for (int j = 0; j < 8; j++) {
        int idx = lane * 8 + j;
        size_t o = (size_t)warp * 256 + idx;
        float v = pooled[o]
                + fmaxf(fpa[o] + bfp[idx], 0.f)
                + fmaxf(fga[o] + bfg[idx], 0.f);
        s += v * Wfc[idx];
    }
    #pragma unroll
    for (int off = 16; off > 0; off >>= 1) s += __shfl_xor_sync(0xFFFFFFFFu, s, off);
    if (lane == 0) out[warp] = s + bfc[0];
}

// ---------------- host launcher -------------------------------------------------
extern "C" void kernel_launch(void* const* d_in, const int* in_sizes, int n_in,
                              void* d_out, int out_size)
{
    const float* x    = (const float*)d_in[0];
    const void*  eraw = d_in[1];
    const void*  braw = d_in[2];
    const float* fpf  = (const float*)d_in[3];
    const float* fgf  = (const float*)d_in[4];
    const float* W1   = (const float*)d_in[5];  const float* b1  = (const float*)d_in[6];
    const float* W2   = (const float*)d_in[7];  const float* b2  = (const float*)d_in[8];
    const float* W3   = (const float*)d_in[9];  const float* b3  = (const float*)d_in[10];
    const float* Wr1  = (const float*)d_in[11]; const float* br1 = (const float*)d_in[12];
    const float* Wr2  = (const float*)d_in[13]; const float* br2 = (const float*)d_in[14];
    const float* Wfp  = (const float*)d_in[15]; const float* bfp = (const float*)d_in[16];
    const float* Wfg  = (const float*)d_in[17]; const float* bfg = (const float*)d_in[18];
    const float* attn_W = (const float*)d_in[19];
    const float* Wfc  = (const float*)d_in[20]; const float* bfc = (const float*)d_in[21];
    float* out = (float*)d_out;

    int N = in_sizes[0] / 64;
    int E = in_sizes[1] / 2;
    int B = in_sizes[3] / 2048;

    __half *xs0, *A1, *A2, *xs1, *A3, *xs2, *x3;
    __half *w1r, *w2s, *w3s, *wattn, *fph, *wfph, *fgp, *wfgp;
    float *work, *dinv, *pooled, *fp, *fg;
    int *eidx, *batch, *deg, *rowptr, *cur, *col, *flag;
    cudaGetSymbolAddress((void**)&eidx,   g_eidx);
    cudaGetSymbolAddress((void**)&batch,  g_batch);
    cudaGetSymbolAddress((void**)&deg,    g_deg);
    cudaGetSymbolAddress((void**)&rowptr, g_rowptr);
    cudaGetSymbolAddress((void**)&cur,    g_cur);
    cudaGetSymbolAddress((void**)&col,    g_col);
    cudaGetSymbolAddress((void**)&flag,   g_flag);
    cudaGetSymbolAddress((void**)&dinv,   g_dinv);
    cudaGetSymbolAddress((void**)&xs0,    g_xs0);
    cudaGetSymbolAddress((void**)&A1,     g_A1);
    cudaGetSymbolAddress((void**)&A2,     g_A2);
    cudaGetSymbolAddress((void**)&xs1,    g_xs1);
    cudaGetSymbolAddress((void**)&A3,     g_A3);
    cudaGetSymbolAddress((void**)&xs2,    g_xs2);
    cudaGetSymbolAddress((void**)&x3,     g_x3);
    cudaGetSymbolAddress((void**)&work,   g_work);
    cudaGetSymbolAddress((void**)&w1r,    g_w1r);
    cudaGetSymbolAddress((void**)&w2s,    g_w2s);
    cudaGetSymbolAddress((void**)&w3s,    g_w3s);
    cudaGetSymbolAddress((void**)&wattn,  g_wattn);
    cudaGetSymbolAddress((void**)&fph,    g_fph);
    cudaGetSymbolAddress((void**)&wfph,   g_wfph);
    cudaGetSymbolAddress((void**)&fgp,    g_fgp);
    cudaGetSymbolAddress((void**)&wfgp,   g_wfgp);
    cudaGetSymbolAddress((void**)&pooled, g_pool);
    cudaGetSymbolAddress((void**)&fp,     g_fp);
    cudaGetSymbolAddress((void**)&fg,     g_fg);

    static int attrSet = 0;
    if (!attrSet) {
        cudaFuncSetAttribute(gemm_h_kernel, cudaFuncAttributeMaxDynamicSharedMemorySize, GEMM_SMEM);
        attrSet = 1;
    }

    cudaMemsetAsync(deg, 0, N * sizeof(int));
    cudaMemsetAsync(cur, 0, N * sizeof(int));
    cudaMemsetAsync(fp,  0, (size_t)B * 256 * sizeof(float));

    // dtype detect + index conversion + degree
    detect_kernel<<<1, 32>>>((const unsigned int*)eraw, flag);
    cvt_edges_kernel<<<(E + 255) / 256, 256>>>(eraw, E, flag, eidx, deg);
    cvt_idx_kernel<<<(N + 255) / 256, 256>>>(braw, N, flag, batch);
    const int* srcA = eidx;
    const int* dstA = eidx + E;

    dinv_kernel<<<(N + 255) / 256, 256>>>(deg, dinv, N);
    scale0_kernel<<<(N * 64 + 255) / 256, 256>>>(x, dinv, xs0, N * 64);

    // all weight prep in one kernel
    prep_kernel<<<(PREP_TOTAL + 255) / 256, 256>>>(
        W1, W2, Wr1, W3, Wr2, attn_W, fpf, Wfp, fgf, Wfg,
        w1r, w2s, w3s, wattn, fph, wfph, fgp, wfgp);

    // CSR
    scan_kernel<<<1, 1024>>>(deg, rowptr, N);
    fill_csr_kernel<<<(E + 255) / 256, 256>>>(srcA, dstA, E, rowptr, cur, col);

    int aggBlocks = (N * 32 + 255) / 256;
    int gy = (N + 127) / 128;

    // fp / fg (fp16; fp split-K 8 with fp32 atomic accum)
    gemm_h_kernel<<<dim3(2, (B + 127) / 128, 8), 256, GEMM_SMEM>>>(
        fph, wfph, nullptr, fp, B, 256, 2048, 256, 256, 1,
        nullptr, nullptr, nullptr, 0, nullptr);
    gemm_h_kernel<<<dim3(2, (B + 127) / 128, 1), 256, GEMM_SMEM>>>(
        fgp, wfgp, nullptr, fg, B, 256, 192, 256, 192, 0,
        nullptr, nullptr, nullptr, 0, nullptr);

    // Layer 1: z1 = agg(xs0); x1 = relu(z1@W1 + b1) -> A2[:,128:256], xs1 = dinv*x1
    aggregate_kernel<64><<<aggBlocks, 256>>>(xs0, rowptr, col, dinv, A1, 64, N);
    gemm_h_kernel<<<dim3(1, gy), 256, GEMM_SMEM>>>(
        A1, w1r, A2 + 128, nullptr, N, 128, 64, 256, 64, 0,
        b1, nullptr, xs1, 128, dinv);

    // Layer 2: z2 = agg(xs1) -> A2[:,0:128]; x2 = relu([z2|x1]@[W2;Wr1] + b2 + br1)
    aggregate_kernel<128><<<aggBlocks, 256>>>(xs1, rowptr, col, dinv, A2, 256, N);
    gemm_h_kernel<<<dim3(2, gy), 256, GEMM_SMEM>>>(
        A2, w2s, A3 + 256, nullptr, N, 256, 256, 512, 256, 0,
        b2, br1, xs2, 256, dinv);

    // Layer 3: z3 = agg(xs2) -> A3[:,0:256]; x3 = relu([z3|x2]@[W3;Wr2] + b3 + br2)
    aggregate_kernel<256><<<aggBlocks, 256>>>(xs2, rowptr, col, dinv, A3, 512, N);
    gemm_h_kernel<<<dim3(2, gy), 256, GEMM_SMEM>>>(
        A3, w3s, x3, nullptr, N, 256, 512, 256, 512, 0,
        b3, br2, nullptr, 0, nullptr);

    // Attention logits (fp32 out — half rounding of O(250) logits would break softmax)
    gemm_h_kernel<<<dim3(2, gy), 256, GEMM_SMEM>>>(
        x3, wattn, nullptr, work, N, 256, 256, 256, 256, 0,
        nullptr, nullptr, nullptr, 0, nullptr);

    // softmax * x3 -> per-graph pooled mean
    softmax_pool_kernel<<<B, 256>>>(work, x3, batch, pooled, N);

    // final projection
    final_kernel<<<(B * 32 + 255) / 256, 256>>>(pooled, fp, fg, bfp, bfg, Wfc, bfc, out, B);
}